// round 1
// baseline (speedup 1.0000x reference)
#include <cuda_runtime.h>
#include <math.h>
#include <stdint.h>

// ---------------- problem constants ----------------
#define Bsz   32
#define Cch   384
#define Hh    56
#define Wwid  56
#define WS    7
#define SSH   3
#define NHd   12
#define Ntok  49
#define HDim  32
#define HIDd  1536
#define NWTOT 2048                 // B * (56/7)^2
#define Mrows (NWTOT*Ntok)         // 100352
#define SCALE 0.17677669529663687f // 32^-0.5

// ---------------- scratch (single static device buffer, ~2.0GB) ----------------
constexpr size_t OFF_XRAW = 0;                                   // [M,384] x in m-order (== shortcut)
constexpr size_t OFF_XLN  = OFF_XRAW + (size_t)Mrows*Cch;        // [M,384] LN1(x)
constexpr size_t OFF_QKV  = OFF_XLN  + (size_t)Mrows*Cch;        // [M,1152]
constexpr size_t OFF_ATT  = OFF_QKV  + (size_t)Mrows*(3*Cch);    // [M,384] attention output
constexpr size_t OFF_Y    = OFF_ATT  + (size_t)Mrows*Cch;        // [M,384] proj + shortcut
constexpr size_t OFF_YLN  = OFF_Y    + (size_t)Mrows*Cch;        // [M,384] LN2(y)
constexpr size_t OFF_H    = OFF_YLN  + (size_t)Mrows*Cch;        // [M,1536] gelu(fc1)
constexpr size_t OFF_FIN  = OFF_H    + (size_t)Mrows*HIDd;       // [M,384] y + mlp
constexpr size_t SCRATCH_FLOATS = OFF_FIN + (size_t)Mrows*Cch;

__device__ float g_scratch[SCRATCH_FLOATS];

// ---------------- helpers ----------------
__device__ __forceinline__ int region(int p) {
    return p < (Hh - WS) ? 0 : (p < (Hh - SSH) ? 1 : 2);
}
__device__ __forceinline__ float gelu_exact(float v) {
    return 0.5f * v * (1.0f + erff(v * 0.70710678118654752f));
}

// ---------------- transpose-in: NCHW -> m-order [M,384] (shift+window partition fused)
__global__ void __launch_bounds__(256) tin_kernel(const float* __restrict__ x) {
    int ct = blockIdx.x;   // channel tile 0..11
    int hh = blockIdx.y;   // shifted row 0..55
    int b  = blockIdx.z;
    __shared__ float tile[32][57];
    int h0 = hh + SSH; if (h0 >= Hh) h0 -= Hh;   // source row in original image
    for (int idx = threadIdx.x; idx < 32*56; idx += 256) {
        int i = idx / 56, ws = idx - i*56;
        tile[i][ws] = x[((size_t)(b*Cch + ct*32 + i))*(Hh*Wwid) + h0*Wwid + ws];
    }
    __syncthreads();
    int wh = hh / WS, r = hh % WS;
    for (int idx = threadIdx.x; idx < 56*32; idx += 256) {
        int t = idx >> 5, i = idx & 31;          // t = shifted col (wwc)
        int wsrc = t + SSH; if (wsrc >= Wwid) wsrc -= Wwid;
        int ww = t / WS, c = t % WS;
        int m = (((b*8 + wh)*8 + ww)*Ntok) + r*WS + c;
        g_scratch[OFF_XRAW + (size_t)m*Cch + ct*32 + i] = tile[i][wsrc];
    }
}

// ---------------- transpose-out: m-order [M,384] -> NCHW (reverse+unshift fused)
__global__ void __launch_bounds__(256) tout_kernel(float* __restrict__ out) {
    int ct = blockIdx.x;
    int h0 = blockIdx.y;   // output row
    int b  = blockIdx.z;
    __shared__ float tile[32][57];
    int hh = h0 - SSH; if (hh < 0) hh += Hh;
    int wh = hh / WS, r = hh % WS;
    for (int idx = threadIdx.x; idx < 56*32; idx += 256) {
        int t = idx >> 5, i = idx & 31;          // t = shifted col
        int ww = t / WS, c = t % WS;
        int m = (((b*8 + wh)*8 + ww)*Ntok) + r*WS + c;
        int w0 = t + SSH; if (w0 >= Wwid) w0 -= Wwid;
        tile[i][w0] = g_scratch[OFF_FIN + (size_t)m*Cch + ct*32 + i];
    }
    __syncthreads();
    for (int idx = threadIdx.x; idx < 32*56; idx += 256) {
        int i = idx / 56, w0 = idx - i*56;
        out[((size_t)(b*Cch + ct*32 + i))*(Hh*Wwid) + h0*Wwid + w0] = tile[i][w0];
    }
}

// ---------------- layernorm over 384-wide rows ----------------
__global__ void __launch_bounds__(128) ln_kernel(size_t Xoff, const float* __restrict__ gam,
                                                 const float* __restrict__ bet, size_t Yoff) {
    int row = blockIdx.x;
    const float* x = g_scratch + Xoff + (size_t)row*Cch;
    float*       y = g_scratch + Yoff + (size_t)row*Cch;
    int c = threadIdx.x;
    float v0 = x[c], v1 = x[c+128], v2 = x[c+256];
    float s = v0+v1+v2, s2 = v0*v0 + v1*v1 + v2*v2;
    #pragma unroll
    for (int o = 16; o; o >>= 1) {
        s  += __shfl_xor_sync(0xffffffffu, s,  o);
        s2 += __shfl_xor_sync(0xffffffffu, s2, o);
    }
    __shared__ float rs[4], rs2[4];
    int wid = c >> 5;
    if ((c & 31) == 0) { rs[wid] = s; rs2[wid] = s2; }
    __syncthreads();
    s  = rs[0]+rs[1]+rs[2]+rs[3];
    s2 = rs2[0]+rs2[1]+rs2[2]+rs2[3];
    float mean = s * (1.0f/Cch);
    float var  = s2 * (1.0f/Cch) - mean*mean;
    float inv  = rsqrtf(var + 1e-5f);
    y[c]     = (v0-mean)*inv*gam[c]     + bet[c];
    y[c+128] = (v1-mean)*inv*gam[c+128] + bet[c+128];
    y[c+256] = (v2-mean)*inv*gam[c+256] + bet[c+256];
}

// ---------------- SGEMM 128x128x8, 256 threads, 8x8 per-thread ----------------
#define EPI_BIAS 0
#define EPI_RES  1
#define EPI_GELU 2

__global__ void __launch_bounds__(256) sgemm_kernel(
    size_t Aoff, const float* __restrict__ B, const float* __restrict__ bias,
    long long resoff, size_t Coff, int M, int N, int K, int epi)
{
    __shared__ float As[8][128];
    __shared__ float Bs[8][128];
    const float* A = g_scratch + Aoff;
    float*       C = g_scratch + Coff;
    int tid = threadIdx.x;
    int brow = blockIdx.y, bcol = blockIdx.x;
    const float* Ablk = A + (size_t)brow*128*K;
    const float* Bblk = B + bcol*128;

    int ty = tid >> 4, tx = tid & 15;
    float acc[8][8];
    #pragma unroll
    for (int i = 0; i < 8; i++)
        #pragma unroll
        for (int j = 0; j < 8; j++) acc[i][j] = 0.f;

    int arow = tid >> 1;                 // 0..127
    int acol = (tid & 1) * 4;            // 0 or 4
    int bkr  = tid >> 5;                 // 0..7
    int bcl  = (tid & 31) * 4;           // 0..124

    for (int k0 = 0; k0 < K; k0 += 8) {
        float4 a = *(const float4*)(Ablk + (size_t)arow*K + k0 + acol);
        As[acol+0][arow] = a.x; As[acol+1][arow] = a.y;
        As[acol+2][arow] = a.z; As[acol+3][arow] = a.w;
        *(float4*)(&Bs[bkr][bcl]) = *(const float4*)(Bblk + (size_t)(k0+bkr)*N + bcl);
        __syncthreads();
        #pragma unroll
        for (int k = 0; k < 8; k++) {
            float ra[8], rb[8];
            #pragma unroll
            for (int i = 0; i < 8; i++) ra[i] = As[k][ty*8 + i];
            #pragma unroll
            for (int j = 0; j < 8; j++) rb[j] = Bs[k][tx*8 + j];
            #pragma unroll
            for (int i = 0; i < 8; i++)
                #pragma unroll
                for (int j = 0; j < 8; j++) acc[i][j] = fmaf(ra[i], rb[j], acc[i][j]);
        }
        __syncthreads();
    }

    const float* res = (resoff >= 0) ? (g_scratch + (size_t)resoff) : nullptr;
    #pragma unroll
    for (int i = 0; i < 8; i++) {
        int row = brow*128 + ty*8 + i;
        #pragma unroll
        for (int j = 0; j < 8; j++) {
            int col = bcol*128 + tx*8 + j;
            float v = acc[i][j] + bias[col];
            if (epi == EPI_GELU)      v = gelu_exact(v);
            else if (epi == EPI_RES)  v += res[(size_t)row*N + col];
            C[(size_t)row*N + col] = v;
        }
    }
}

// ---------------- windowed attention: one block per (window, head) ----------------
__global__ void __launch_bounds__(128) attn_kernel(const float* __restrict__ rpb) {
    int blk = blockIdx.x;
    int h = blk % NHd;
    int w = blk / NHd;                 // 0..2047
    int ww = w & 7, wh = (w >> 3) & 7;
    int m0 = w * Ntok;
    __shared__ float q[Ntok][33], kk[Ntok][33], vv[Ntok][33];
    __shared__ float sc[Ntok][50];
    __shared__ int   rid[Ntok];
    int tid = threadIdx.x;

    const float* qkv = g_scratch + OFF_QKV;
    for (int idx = tid; idx < Ntok*HDim; idx += 128) {
        int i = idx >> 5, d = idx & 31;
        size_t base = (size_t)(m0 + i)*(3*Cch) + h*HDim + d;
        q [i][d] = qkv[base]        * SCALE;
        kk[i][d] = qkv[base + Cch];
        vv[i][d] = qkv[base + 2*Cch];
    }
    if (tid < Ntok) {
        int r = tid / WS, c = tid % WS;
        rid[tid] = region(wh*WS + r)*3 + region(ww*WS + c);
    }
    __syncthreads();

    for (int idx = tid; idx < Ntok*Ntok; idx += 128) {
        int i = idx / Ntok, j = idx - i*Ntok;
        float s = 0.f;
        #pragma unroll
        for (int d = 0; d < HDim; d++) s = fmaf(q[i][d], kk[j][d], s);
        int ri = i / WS, ci = i % WS, rj = j / WS, cj = j % WS;
        int rpi = (ri - rj + WS - 1)*(2*WS - 1) + (ci - cj + WS - 1);
        s += rpb[rpi*NHd + h];
        if (rid[i] != rid[j]) s -= 100.0f;
        sc[i][j] = s;
    }
    __syncthreads();

    if (tid < Ntok) {
        float mx = -1e30f;
        #pragma unroll 7
        for (int j = 0; j < Ntok; j++) mx = fmaxf(mx, sc[tid][j]);
        float sum = 0.f;
        #pragma unroll 7
        for (int j = 0; j < Ntok; j++) { float e = expf(sc[tid][j] - mx); sc[tid][j] = e; sum += e; }
        float inv = 1.0f / sum;
        #pragma unroll 7
        for (int j = 0; j < Ntok; j++) sc[tid][j] *= inv;
    }
    __syncthreads();

    float* att = g_scratch + OFF_ATT;
    for (int idx = tid; idx < Ntok*HDim; idx += 128) {
        int i = idx >> 5, d = idx & 31;
        float o = 0.f;
        #pragma unroll
        for (int j = 0; j < Ntok; j++) o = fmaf(sc[i][j], vv[j][d], o);
        att[(size_t)(m0 + i)*Cch + h*HDim + d] = o;
    }
}

// ---------------- launch ----------------
extern "C" void kernel_launch(void* const* d_in, const int* in_sizes, int n_in,
                              void* d_out, int out_size) {
    const float* x      = (const float*)d_in[0];
    const float* qkv_w  = (const float*)d_in[1];
    const float* qkv_b  = (const float*)d_in[2];
    const float* proj_w = (const float*)d_in[3];
    const float* proj_b = (const float*)d_in[4];
    const float* rpb    = (const float*)d_in[5];
    const float* n1w    = (const float*)d_in[6];
    const float* n1b    = (const float*)d_in[7];
    const float* n2w    = (const float*)d_in[8];
    const float* n2b    = (const float*)d_in[9];
    const float* fc1w   = (const float*)d_in[10];
    const float* fc1b   = (const float*)d_in[11];
    const float* fc2w   = (const float*)d_in[12];
    const float* fc2b   = (const float*)d_in[13];
    float* out = (float*)d_out;

    // 1. NCHW -> m-order tokens (shift + window partition fused)
    tin_kernel<<<dim3(12, 56, 32), 256>>>(x);
    // 2. LN1
    ln_kernel<<<Mrows, 128>>>(OFF_XRAW, n1w, n1b, OFF_XLN);
    // 3. QKV GEMM [M,384]x[384,1152] + bias
    sgemm_kernel<<<dim3(1152/128, Mrows/128), 256>>>(OFF_XLN, qkv_w, qkv_b, -1, OFF_QKV,
                                                     Mrows, 1152, Cch, EPI_BIAS);
    // 4. windowed attention (bias + shift mask + softmax + AV)
    attn_kernel<<<NWTOT * NHd, 128>>>(rpb);
    // 5. proj GEMM + bias + shortcut  -> y
    sgemm_kernel<<<dim3(384/128, Mrows/128), 256>>>(OFF_ATT, proj_w, proj_b, (long long)OFF_XRAW,
                                                    OFF_Y, Mrows, Cch, Cch, EPI_RES);
    // 6. LN2
    ln_kernel<<<Mrows, 128>>>(OFF_Y, n2w, n2b, OFF_YLN);
    // 7. FC1 GEMM + bias + exact GELU
    sgemm_kernel<<<dim3(1536/128, Mrows/128), 256>>>(OFF_YLN, fc1w, fc1b, -1, OFF_H,
                                                     Mrows, HIDd, Cch, EPI_GELU);
    // 8. FC2 GEMM + bias + residual(y) -> final
    sgemm_kernel<<<dim3(384/128, Mrows/128), 256>>>(OFF_H, fc2w, fc2b, (long long)OFF_Y,
                                                    OFF_FIN, Mrows, Cch, HIDd, EPI_RES);
    // 9. m-order -> NCHW output (reverse + unshift fused)
    tout_kernel<<<dim3(12, 56, 32), 256>>>(out);
}

// round 2
// speedup vs baseline: 1.3463x; 1.3463x over previous
#include <cuda_runtime.h>
#include <math.h>
#include <stdint.h>

// ---------------- problem constants ----------------
#define Bsz   32
#define Cch   384
#define Hh    56
#define Wwid  56
#define WS    7
#define SSH   3
#define NHd   12
#define Ntok  49
#define HDim  32
#define HIDd  1536
#define NWTOT 2048                 // B * (56/7)^2
#define Mrows (NWTOT*Ntok)         // 100352
#define SCALE 0.17677669529663687f // 32^-0.5

// ---------------- scratch ----------------
constexpr size_t OFF_XRAW = 0;
constexpr size_t OFF_XLN  = OFF_XRAW + (size_t)Mrows*Cch;
constexpr size_t OFF_QKV  = OFF_XLN  + (size_t)Mrows*Cch;
constexpr size_t OFF_ATT  = OFF_QKV  + (size_t)Mrows*(3*Cch);
constexpr size_t OFF_Y    = OFF_ATT  + (size_t)Mrows*Cch;
constexpr size_t OFF_YLN  = OFF_Y    + (size_t)Mrows*Cch;
constexpr size_t OFF_H    = OFF_YLN  + (size_t)Mrows*Cch;
constexpr size_t OFF_FIN  = OFF_H    + (size_t)Mrows*HIDd;
constexpr size_t SCRATCH_FLOATS = OFF_FIN + (size_t)Mrows*Cch;

__device__ float g_scratch[SCRATCH_FLOATS];

// ---------------- helpers ----------------
__device__ __forceinline__ int region(int p) {
    return p < (Hh - WS) ? 0 : (p < (Hh - SSH) ? 1 : 2);
}
__device__ __forceinline__ float gelu_exact(float v) {
    return 0.5f * v * (1.0f + erff(v * 0.70710678118654752f));
}
__device__ __forceinline__ uint32_t f2tf(float f) {
    uint32_t r; asm("cvt.rna.tf32.f32 %0, %1;" : "=r"(r) : "f"(f)); return r;
}
__device__ __forceinline__ void mma_tf32(float c[4], const uint32_t a[4], const uint32_t b[2]) {
    asm volatile(
        "mma.sync.aligned.m16n8k8.row.col.f32.tf32.tf32.f32 "
        "{%0,%1,%2,%3}, {%4,%5,%6,%7}, {%8,%9}, {%0,%1,%2,%3};\n"
        : "+f"(c[0]), "+f"(c[1]), "+f"(c[2]), "+f"(c[3])
        : "r"(a[0]), "r"(a[1]), "r"(a[2]), "r"(a[3]), "r"(b[0]), "r"(b[1]));
}

// ---------------- transpose-in ----------------
__global__ void __launch_bounds__(256) tin_kernel(const float* __restrict__ x) {
    int ct = blockIdx.x, hh = blockIdx.y, b = blockIdx.z;
    __shared__ float tile[32][57];
    int h0 = hh + SSH; if (h0 >= Hh) h0 -= Hh;
    for (int idx = threadIdx.x; idx < 32*56; idx += 256) {
        int i = idx / 56, ws = idx - i*56;
        tile[i][ws] = x[((size_t)(b*Cch + ct*32 + i))*(Hh*Wwid) + h0*Wwid + ws];
    }
    __syncthreads();
    int wh = hh / WS, r = hh % WS;
    for (int idx = threadIdx.x; idx < 56*32; idx += 256) {
        int t = idx >> 5, i = idx & 31;
        int wsrc = t + SSH; if (wsrc >= Wwid) wsrc -= Wwid;
        int ww = t / WS, c = t % WS;
        int m = (((b*8 + wh)*8 + ww)*Ntok) + r*WS + c;
        g_scratch[OFF_XRAW + (size_t)m*Cch + ct*32 + i] = tile[i][wsrc];
    }
}

// ---------------- transpose-out ----------------
__global__ void __launch_bounds__(256) tout_kernel(float* __restrict__ out) {
    int ct = blockIdx.x, h0 = blockIdx.y, b = blockIdx.z;
    __shared__ float tile[32][57];
    int hh = h0 - SSH; if (hh < 0) hh += Hh;
    int wh = hh / WS, r = hh % WS;
    for (int idx = threadIdx.x; idx < 56*32; idx += 256) {
        int t = idx >> 5, i = idx & 31;
        int ww = t / WS, c = t % WS;
        int m = (((b*8 + wh)*8 + ww)*Ntok) + r*WS + c;
        int w0 = t + SSH; if (w0 >= Wwid) w0 -= Wwid;
        tile[i][w0] = g_scratch[OFF_FIN + (size_t)m*Cch + ct*32 + i];
    }
    __syncthreads();
    for (int idx = threadIdx.x; idx < 32*56; idx += 256) {
        int i = idx / 56, w0 = idx - i*56;
        out[((size_t)(b*Cch + ct*32 + i))*(Hh*Wwid) + h0*Wwid + w0] = tile[i][w0];
    }
}

// ---------------- layernorm ----------------
__global__ void __launch_bounds__(128) ln_kernel(size_t Xoff, const float* __restrict__ gam,
                                                 const float* __restrict__ bet, size_t Yoff) {
    int row = blockIdx.x;
    const float* x = g_scratch + Xoff + (size_t)row*Cch;
    float*       y = g_scratch + Yoff + (size_t)row*Cch;
    int c = threadIdx.x;
    float v0 = x[c], v1 = x[c+128], v2 = x[c+256];
    float s = v0+v1+v2, s2 = v0*v0 + v1*v1 + v2*v2;
    #pragma unroll
    for (int o = 16; o; o >>= 1) {
        s  += __shfl_xor_sync(0xffffffffu, s,  o);
        s2 += __shfl_xor_sync(0xffffffffu, s2, o);
    }
    __shared__ float rs[4], rs2[4];
    int wid = c >> 5;
    if ((c & 31) == 0) { rs[wid] = s; rs2[wid] = s2; }
    __syncthreads();
    s  = rs[0]+rs[1]+rs[2]+rs[3];
    s2 = rs2[0]+rs2[1]+rs2[2]+rs2[3];
    float mean = s * (1.0f/Cch);
    float var  = s2 * (1.0f/Cch) - mean*mean;
    float inv  = rsqrtf(var + 1e-5f);
    y[c]     = (v0-mean)*inv*gam[c]     + bet[c];
    y[c+128] = (v1-mean)*inv*gam[c+128] + bet[c+128];
    y[c+256] = (v2-mean)*inv*gam[c+256] + bet[c+256];
}

// ---------------- TF32 tensor-core GEMM 128x128 block, 2x4 warps, 64x32 warp tile
#define EPI_BIAS 0
#define EPI_RES  1
#define EPI_GELU 2

// As stride 12 floats (conflict-free fragment loads), Bs stride 136
__global__ void __launch_bounds__(256) tgemm_kernel(
    size_t Aoff, const float* __restrict__ B, const float* __restrict__ bias,
    long long resoff, size_t Coff, int M, int N, int K, int epi)
{
    __shared__ uint32_t As[128*12];
    __shared__ uint32_t Bs[8*136];
    const float* A = g_scratch + Aoff;
    float*       C = g_scratch + Coff;
    int tid = threadIdx.x;
    int warp = tid >> 5, lane = tid & 31;
    int wrow = warp >> 2, wcol = warp & 3;     // 2 x 4 warp grid
    int g = lane >> 2, qc = lane & 3;
    int brow = blockIdx.y, bcol = blockIdx.x;

    const float* Ablk = A + (size_t)brow*128*K;
    const float* Bblk = B + bcol*128;

    float acc[4][4][4];
    #pragma unroll
    for (int i = 0; i < 4; i++)
        #pragma unroll
        for (int j = 0; j < 4; j++)
            #pragma unroll
            for (int r = 0; r < 4; r++) acc[i][j][r] = 0.f;

    int arow = tid >> 1;            // 0..127
    int acol = (tid & 1) * 4;       // 0 / 4
    int bkr  = tid >> 5;            // 0..7
    int bcl  = (tid & 31) * 4;      // 0..124

    for (int k0 = 0; k0 < K; k0 += 8) {
        float4 a = *(const float4*)(Ablk + (size_t)arow*K + k0 + acol);
        uint4 av = { f2tf(a.x), f2tf(a.y), f2tf(a.z), f2tf(a.w) };
        *(uint4*)(&As[arow*12 + acol]) = av;
        float4 b = *(const float4*)(Bblk + (size_t)(k0+bkr)*N + bcl);
        uint4 bv = { f2tf(b.x), f2tf(b.y), f2tf(b.z), f2tf(b.w) };
        *(uint4*)(&Bs[bkr*136 + bcl]) = bv;
        __syncthreads();

        uint32_t af[4][4];
        #pragma unroll
        for (int i = 0; i < 4; i++) {
            int r = wrow*64 + i*16 + g;
            af[i][0] = As[r*12 + qc];
            af[i][1] = As[(r+8)*12 + qc];
            af[i][2] = As[r*12 + qc + 4];
            af[i][3] = As[(r+8)*12 + qc + 4];
        }
        uint32_t bf[4][2];
        #pragma unroll
        for (int j = 0; j < 4; j++) {
            int cidx = wcol*32 + j*8 + g;
            bf[j][0] = Bs[qc*136 + cidx];
            bf[j][1] = Bs[(qc+4)*136 + cidx];
        }
        #pragma unroll
        for (int i = 0; i < 4; i++)
            #pragma unroll
            for (int j = 0; j < 4; j++)
                mma_tf32(acc[i][j], af[i], bf[j]);
        __syncthreads();
    }

    const float* res = (resoff >= 0) ? (g_scratch + (size_t)resoff) : nullptr;
    #pragma unroll
    for (int i = 0; i < 4; i++) {
        int r0 = brow*128 + wrow*64 + i*16 + g;
        #pragma unroll
        for (int j = 0; j < 4; j++) {
            int cb = bcol*128 + wcol*32 + j*8 + qc*2;
            float bx = bias[cb], by = bias[cb+1];
            #pragma unroll
            for (int half = 0; half < 2; half++) {
                int row = r0 + half*8;
                float vx = acc[i][j][half*2]   + bx;
                float vy = acc[i][j][half*2+1] + by;
                if (epi == EPI_GELU) { vx = gelu_exact(vx); vy = gelu_exact(vy); }
                else if (epi == EPI_RES) {
                    float2 rr = *(const float2*)(res + (size_t)row*N + cb);
                    vx += rr.x; vy += rr.y;
                }
                float2 o = {vx, vy};
                *(float2*)(C + (size_t)row*N + cb) = o;
            }
        }
    }
}

// ---------------- windowed attention ----------------
__global__ void __launch_bounds__(128) attn_kernel(const float* __restrict__ rpb) {
    int blk = blockIdx.x;
    int h = blk % NHd;
    int w = blk / NHd;
    int ww = w & 7, wh = (w >> 3) & 7;
    int m0 = w * Ntok;
    __shared__ float q[Ntok][33], kk[Ntok][33], vv[Ntok][33];
    __shared__ float sc[Ntok][50];
    __shared__ int   rid[Ntok];
    int tid = threadIdx.x;

    const float* qkv = g_scratch + OFF_QKV;
    for (int idx = tid; idx < Ntok*HDim; idx += 128) {
        int i = idx >> 5, d = idx & 31;
        size_t base = (size_t)(m0 + i)*(3*Cch) + h*HDim + d;
        q [i][d] = qkv[base]        * SCALE;
        kk[i][d] = qkv[base + Cch];
        vv[i][d] = qkv[base + 2*Cch];
    }
    if (tid < Ntok) {
        int r = tid / WS, c = tid % WS;
        rid[tid] = region(wh*WS + r)*3 + region(ww*WS + c);
    }
    __syncthreads();

    for (int idx = tid; idx < Ntok*Ntok; idx += 128) {
        int i = idx / Ntok, j = idx - i*Ntok;
        float s = 0.f;
        #pragma unroll
        for (int d = 0; d < HDim; d++) s = fmaf(q[i][d], kk[j][d], s);
        int ri = i / WS, ci = i % WS, rj = j / WS, cj = j % WS;
        int rpi = (ri - rj + WS - 1)*(2*WS - 1) + (ci - cj + WS - 1);
        s += rpb[rpi*NHd + h];
        if (rid[i] != rid[j]) s -= 100.0f;
        sc[i][j] = s;
    }
    __syncthreads();

    if (tid < Ntok) {
        float mx = -1e30f;
        #pragma unroll 7
        for (int j = 0; j < Ntok; j++) mx = fmaxf(mx, sc[tid][j]);
        float sum = 0.f;
        #pragma unroll 7
        for (int j = 0; j < Ntok; j++) { float e = expf(sc[tid][j] - mx); sc[tid][j] = e; sum += e; }
        float inv = 1.0f / sum;
        #pragma unroll 7
        for (int j = 0; j < Ntok; j++) sc[tid][j] *= inv;
    }
    __syncthreads();

    float* att = g_scratch + OFF_ATT;
    for (int idx = tid; idx < Ntok*HDim; idx += 128) {
        int i = idx >> 5, d = idx & 31;
        float o = 0.f;
        #pragma unroll
        for (int j = 0; j < Ntok; j++) o = fmaf(sc[i][j], vv[j][d], o);
        att[(size_t)(m0 + i)*Cch + h*HDim + d] = o;
    }
}

// ---------------- launch ----------------
extern "C" void kernel_launch(void* const* d_in, const int* in_sizes, int n_in,
                              void* d_out, int out_size) {
    const float* x      = (const float*)d_in[0];
    const float* qkv_w  = (const float*)d_in[1];
    const float* qkv_b  = (const float*)d_in[2];
    const float* proj_w = (const float*)d_in[3];
    const float* proj_b = (const float*)d_in[4];
    const float* rpb    = (const float*)d_in[5];
    const float* n1w    = (const float*)d_in[6];
    const float* n1b    = (const float*)d_in[7];
    const float* n2w    = (const float*)d_in[8];
    const float* n2b    = (const float*)d_in[9];
    const float* fc1w   = (const float*)d_in[10];
    const float* fc1b   = (const float*)d_in[11];
    const float* fc2w   = (const float*)d_in[12];
    const float* fc2b   = (const float*)d_in[13];
    float* out = (float*)d_out;

    tin_kernel<<<dim3(12, 56, 32), 256>>>(x);
    ln_kernel<<<Mrows, 128>>>(OFF_XRAW, n1w, n1b, OFF_XLN);
    tgemm_kernel<<<dim3(1152/128, Mrows/128), 256>>>(OFF_XLN, qkv_w, qkv_b, -1, OFF_QKV,
                                                     Mrows, 1152, Cch, EPI_BIAS);
    attn_kernel<<<NWTOT * NHd, 128>>>(rpb);
    tgemm_kernel<<<dim3(384/128, Mrows/128), 256>>>(OFF_ATT, proj_w, proj_b, (long long)OFF_XRAW,
                                                    OFF_Y, Mrows, Cch, Cch, EPI_RES);
    ln_kernel<<<Mrows, 128>>>(OFF_Y, n2w, n2b, OFF_YLN);
    tgemm_kernel<<<dim3(1536/128, Mrows/128), 256>>>(OFF_YLN, fc1w, fc1b, -1, OFF_H,
                                                     Mrows, HIDd, Cch, EPI_GELU);
    tgemm_kernel<<<dim3(384/128, Mrows/128), 256>>>(OFF_H, fc2w, fc2b, (long long)OFF_Y,
                                                    OFF_FIN, Mrows, Cch, HIDd, EPI_RES);
    tout_kernel<<<dim3(12, 56, 32), 256>>>(out);
}

// round 3
// speedup vs baseline: 2.2659x; 1.6831x over previous
#include <cuda_runtime.h>
#include <math.h>
#include <stdint.h>

// ---------------- problem constants ----------------
#define Bsz   32
#define Cch   384
#define Hh    56
#define Wwid  56
#define WS    7
#define SSH   3
#define NHd   12
#define Ntok  49
#define HDim  32
#define HIDd  1536
#define NWTOT 2048
#define Mrows (NWTOT*Ntok)         // 100352
#define SCALE 0.17677669529663687f

// ---------------- scratch ----------------
constexpr size_t OFF_XRAW = 0;
constexpr size_t OFF_XLN  = OFF_XRAW + (size_t)Mrows*Cch;
constexpr size_t OFF_QKV  = OFF_XLN  + (size_t)Mrows*Cch;
constexpr size_t OFF_ATT  = OFF_QKV  + (size_t)Mrows*(3*Cch);
constexpr size_t OFF_Y    = OFF_ATT  + (size_t)Mrows*Cch;
constexpr size_t OFF_YLN  = OFF_Y    + (size_t)Mrows*Cch;
constexpr size_t OFF_H    = OFF_YLN  + (size_t)Mrows*Cch;
constexpr size_t OFF_FIN  = OFF_H    + (size_t)Mrows*HIDd;
constexpr size_t SCRATCH_FLOATS = OFF_FIN + (size_t)Mrows*Cch;

__device__ float g_scratch[SCRATCH_FLOATS];

// ---------------- helpers ----------------
__device__ __forceinline__ int region(int p) {
    return p < (Hh - WS) ? 0 : (p < (Hh - SSH) ? 1 : 2);
}
__device__ __forceinline__ float gelu_exact(float v) {
    return 0.5f * v * (1.0f + erff(v * 0.70710678118654752f));
}
__device__ __forceinline__ uint32_t f2tf(float f) {
    uint32_t r; asm("cvt.rna.tf32.f32 %0, %1;" : "=r"(r) : "f"(f)); return r;
}
__device__ __forceinline__ void mma_tf32(float c[4], const uint32_t a[4], const uint32_t b[2]) {
    asm volatile(
        "mma.sync.aligned.m16n8k8.row.col.f32.tf32.tf32.f32 "
        "{%0,%1,%2,%3}, {%4,%5,%6,%7}, {%8,%9}, {%0,%1,%2,%3};\n"
        : "+f"(c[0]), "+f"(c[1]), "+f"(c[2]), "+f"(c[3])
        : "r"(a[0]), "r"(a[1]), "r"(a[2]), "r"(a[3]), "r"(b[0]), "r"(b[1]));
}

// ---------------- transpose-in ----------------
__global__ void __launch_bounds__(256) tin_kernel(const float* __restrict__ x) {
    int ct = blockIdx.x, hh = blockIdx.y, b = blockIdx.z;
    __shared__ float tile[32][57];
    int h0 = hh + SSH; if (h0 >= Hh) h0 -= Hh;
    for (int idx = threadIdx.x; idx < 32*56; idx += 256) {
        int i = idx / 56, ws = idx - i*56;
        tile[i][ws] = x[((size_t)(b*Cch + ct*32 + i))*(Hh*Wwid) + h0*Wwid + ws];
    }
    __syncthreads();
    int wh = hh / WS, r = hh % WS;
    for (int idx = threadIdx.x; idx < 56*32; idx += 256) {
        int t = idx >> 5, i = idx & 31;
        int wsrc = t + SSH; if (wsrc >= Wwid) wsrc -= Wwid;
        int ww = t / WS, c = t % WS;
        int m = (((b*8 + wh)*8 + ww)*Ntok) + r*WS + c;
        g_scratch[OFF_XRAW + (size_t)m*Cch + ct*32 + i] = tile[i][wsrc];
    }
}

// ---------------- transpose-out ----------------
__global__ void __launch_bounds__(256) tout_kernel(float* __restrict__ out) {
    int ct = blockIdx.x, h0 = blockIdx.y, b = blockIdx.z;
    __shared__ float tile[32][57];
    int hh = h0 - SSH; if (hh < 0) hh += Hh;
    int wh = hh / WS, r = hh % WS;
    for (int idx = threadIdx.x; idx < 56*32; idx += 256) {
        int t = idx >> 5, i = idx & 31;
        int ww = t / WS, c = t % WS;
        int m = (((b*8 + wh)*8 + ww)*Ntok) + r*WS + c;
        int w0 = t + SSH; if (w0 >= Wwid) w0 -= Wwid;
        tile[i][w0] = g_scratch[OFF_FIN + (size_t)m*Cch + ct*32 + i];
    }
    __syncthreads();
    for (int idx = threadIdx.x; idx < 32*56; idx += 256) {
        int i = idx / 56, w0 = idx - i*56;
        out[((size_t)(b*Cch + ct*32 + i))*(Hh*Wwid) + h0*Wwid + w0] = tile[i][w0];
    }
}

// ---------------- layernorm ----------------
__global__ void __launch_bounds__(128) ln_kernel(size_t Xoff, const float* __restrict__ gam,
                                                 const float* __restrict__ bet, size_t Yoff) {
    int row = blockIdx.x;
    const float* x = g_scratch + Xoff + (size_t)row*Cch;
    float*       y = g_scratch + Yoff + (size_t)row*Cch;
    int c = threadIdx.x;
    float v0 = x[c], v1 = x[c+128], v2 = x[c+256];
    float s = v0+v1+v2, s2 = v0*v0 + v1*v1 + v2*v2;
    #pragma unroll
    for (int o = 16; o; o >>= 1) {
        s  += __shfl_xor_sync(0xffffffffu, s,  o);
        s2 += __shfl_xor_sync(0xffffffffu, s2, o);
    }
    __shared__ float rs[4], rs2[4];
    int wid = c >> 5;
    if ((c & 31) == 0) { rs[wid] = s; rs2[wid] = s2; }
    __syncthreads();
    s  = rs[0]+rs[1]+rs[2]+rs[3];
    s2 = rs2[0]+rs2[1]+rs2[2]+rs2[3];
    float mean = s * (1.0f/Cch);
    float var  = s2 * (1.0f/Cch) - mean*mean;
    float inv  = rsqrtf(var + 1e-5f);
    y[c]     = (v0-mean)*inv*gam[c]     + bet[c];
    y[c+128] = (v1-mean)*inv*gam[c+128] + bet[c+128];
    y[c+256] = (v2-mean)*inv*gam[c+256] + bet[c+256];
}

// ---------------- TF32 GEMM: 128x128 block, BK=16, double-buffered, 2x4 warps
#define EPI_BIAS 0
#define EPI_RES  1
#define EPI_GELU 2

#define AST 20   // As row stride (floats)
#define BST 136  // Bs row stride (floats)

__global__ void __launch_bounds__(256, 2) tgemm_kernel(
    size_t Aoff, const float* __restrict__ B, const float* __restrict__ bias,
    long long resoff, size_t Coff, int M, int N, int K, int epi)
{
    __shared__ uint32_t As[2][128*AST];
    __shared__ uint32_t Bs[2][16*BST];
    const float* A = g_scratch + Aoff;
    float*       C = g_scratch + Coff;
    int tid = threadIdx.x;
    int warp = tid >> 5, lane = tid & 31;
    int wrow = warp >> 2, wcol = warp & 3;
    int g = lane >> 2, qc = lane & 3;
    int brow = blockIdx.y, bcol = blockIdx.x;

    const float* Ablk = A + (size_t)brow*128*K;
    const float* Bblk = B + bcol*128;

    int arow = tid >> 1;            // 0..127
    int akc  = (tid & 1) * 8;       // 0 / 8
    int bkr  = tid >> 4;            // 0..15
    int bcl  = (tid & 15) * 8;      // 0..120

    float acc[4][4][4];
    #pragma unroll
    for (int i = 0; i < 4; i++)
        #pragma unroll
        for (int j = 0; j < 4; j++)
            #pragma unroll
            for (int r = 0; r < 4; r++) acc[i][j][r] = 0.f;

    // prologue: load tile 0
    float4 a0 = *(const float4*)(Ablk + (size_t)arow*K + akc);
    float4 a1 = *(const float4*)(Ablk + (size_t)arow*K + akc + 4);
    float4 b0 = *(const float4*)(Bblk + (size_t)bkr*N + bcl);
    float4 b1 = *(const float4*)(Bblk + (size_t)bkr*N + bcl + 4);
    {
        uint4 av0 = { f2tf(a0.x), f2tf(a0.y), f2tf(a0.z), f2tf(a0.w) };
        uint4 av1 = { f2tf(a1.x), f2tf(a1.y), f2tf(a1.z), f2tf(a1.w) };
        *(uint4*)(&As[0][arow*AST + akc])     = av0;
        *(uint4*)(&As[0][arow*AST + akc + 4]) = av1;
        uint4 bv0 = { f2tf(b0.x), f2tf(b0.y), f2tf(b0.z), f2tf(b0.w) };
        uint4 bv1 = { f2tf(b1.x), f2tf(b1.y), f2tf(b1.z), f2tf(b1.w) };
        *(uint4*)(&Bs[0][bkr*BST + bcl])     = bv0;
        *(uint4*)(&Bs[0][bkr*BST + bcl + 4]) = bv1;
    }
    __syncthreads();

    int nk = K >> 4;
    for (int kt = 0; kt < nk; kt++) {
        int cur = kt & 1;
        if (kt + 1 < nk) {
            const float* Ap = Ablk + (size_t)arow*K + (kt+1)*16 + akc;
            a0 = *(const float4*)(Ap);
            a1 = *(const float4*)(Ap + 4);
            const float* Bp = Bblk + (size_t)((kt+1)*16 + bkr)*N + bcl;
            b0 = *(const float4*)(Bp);
            b1 = *(const float4*)(Bp + 4);
        }
        #pragma unroll
        for (int sub = 0; sub < 2; sub++) {
            uint32_t af[4][4];
            #pragma unroll
            for (int i = 0; i < 4; i++) {
                int r = wrow*64 + i*16 + g;
                int kb = sub*8 + qc;
                af[i][0] = As[cur][r*AST + kb];
                af[i][1] = As[cur][(r+8)*AST + kb];
                af[i][2] = As[cur][r*AST + kb + 4];
                af[i][3] = As[cur][(r+8)*AST + kb + 4];
            }
            uint32_t bf[4][2];
            #pragma unroll
            for (int j = 0; j < 4; j++) {
                int cidx = wcol*32 + j*8 + g;
                bf[j][0] = Bs[cur][(sub*8 + qc)*BST + cidx];
                bf[j][1] = Bs[cur][(sub*8 + qc + 4)*BST + cidx];
            }
            #pragma unroll
            for (int i = 0; i < 4; i++)
                #pragma unroll
                for (int j = 0; j < 4; j++)
                    mma_tf32(acc[i][j], af[i], bf[j]);
        }
        if (kt + 1 < nk) {
            int nxt = cur ^ 1;
            uint4 av0 = { f2tf(a0.x), f2tf(a0.y), f2tf(a0.z), f2tf(a0.w) };
            uint4 av1 = { f2tf(a1.x), f2tf(a1.y), f2tf(a1.z), f2tf(a1.w) };
            *(uint4*)(&As[nxt][arow*AST + akc])     = av0;
            *(uint4*)(&As[nxt][arow*AST + akc + 4]) = av1;
            uint4 bv0 = { f2tf(b0.x), f2tf(b0.y), f2tf(b0.z), f2tf(b0.w) };
            uint4 bv1 = { f2tf(b1.x), f2tf(b1.y), f2tf(b1.z), f2tf(b1.w) };
            *(uint4*)(&Bs[nxt][bkr*BST + bcl])     = bv0;
            *(uint4*)(&Bs[nxt][bkr*BST + bcl + 4]) = bv1;
        }
        __syncthreads();
    }

    const float* res = (resoff >= 0) ? (g_scratch + (size_t)resoff) : nullptr;
    #pragma unroll
    for (int i = 0; i < 4; i++) {
        int r0 = brow*128 + wrow*64 + i*16 + g;
        #pragma unroll
        for (int j = 0; j < 4; j++) {
            int cb = bcol*128 + wcol*32 + j*8 + qc*2;
            float bx = bias[cb], by = bias[cb+1];
            #pragma unroll
            for (int half = 0; half < 2; half++) {
                int row = r0 + half*8;
                float vx = acc[i][j][half*2]   + bx;
                float vy = acc[i][j][half*2+1] + by;
                if (epi == EPI_GELU) { vx = gelu_exact(vx); vy = gelu_exact(vy); }
                else if (epi == EPI_RES) {
                    float2 rr = *(const float2*)(res + (size_t)row*N + cb);
                    vx += rr.x; vy += rr.y;
                }
                float2 o = {vx, vy};
                *(float2*)(C + (size_t)row*N + cb) = o;
            }
        }
    }
}

// ---------------- windowed attention (vectorized, 2x2 register-blocked QK) ----
__global__ void __launch_bounds__(128) attn_kernel(const float* __restrict__ rpb) {
    int blk = blockIdx.x;
    int h = blk % NHd;
    int w = blk / NHd;
    int ww = w & 7, wh = (w >> 3) & 7;
    int m0 = w * Ntok;
    __shared__ float q[Ntok][36], kk[Ntok][36], vv[Ntok][36];
    __shared__ float sc[Ntok][50];
    __shared__ int   rid[Ntok];
    int tid = threadIdx.x;

    const float* qkv = g_scratch + OFF_QKV;
    for (int idx = tid; idx < Ntok*8; idx += 128) {
        int i = idx >> 3, dq = (idx & 7) * 4;
        size_t base = (size_t)(m0 + i)*(3*Cch) + h*HDim + dq;
        float4 qa = *(const float4*)(qkv + base);
        float4 ka = *(const float4*)(qkv + base + Cch);
        float4 va = *(const float4*)(qkv + base + 2*Cch);
        qa.x *= SCALE; qa.y *= SCALE; qa.z *= SCALE; qa.w *= SCALE;
        *(float4*)(&q [i][dq]) = qa;
        *(float4*)(&kk[i][dq]) = ka;
        *(float4*)(&vv[i][dq]) = va;
    }
    if (tid < Ntok) {
        int r = tid / WS, c = tid % WS;
        rid[tid] = region(wh*WS + r)*3 + region(ww*WS + c);
    }
    __syncthreads();

    // QK^T + bias + mask: 2x2 register blocking over (i,j)
    for (int t = tid; t < 625; t += 128) {
        int i0 = t / 25, j0 = t % 25;
        int ia = i0*2, ja = j0*2;
        int ib = ia + 1 < Ntok ? ia + 1 : ia;
        int jb = ja + 1 < Ntok ? ja + 1 : ja;
        float s00 = 0.f, s01 = 0.f, s10 = 0.f, s11 = 0.f;
        #pragma unroll
        for (int d = 0; d < HDim; d += 4) {
            float4 qa = *(const float4*)(&q[ia][d]);
            float4 qb = *(const float4*)(&q[ib][d]);
            float4 ka = *(const float4*)(&kk[ja][d]);
            float4 kb = *(const float4*)(&kk[jb][d]);
            s00 = fmaf(qa.x,ka.x, fmaf(qa.y,ka.y, fmaf(qa.z,ka.z, fmaf(qa.w,ka.w, s00))));
            s01 = fmaf(qa.x,kb.x, fmaf(qa.y,kb.y, fmaf(qa.z,kb.z, fmaf(qa.w,kb.w, s01))));
            s10 = fmaf(qb.x,ka.x, fmaf(qb.y,ka.y, fmaf(qb.z,ka.z, fmaf(qb.w,ka.w, s10))));
            s11 = fmaf(qb.x,kb.x, fmaf(qb.y,kb.y, fmaf(qb.z,kb.z, fmaf(qb.w,kb.w, s11))));
        }
        #pragma unroll
        for (int u = 0; u < 4; u++) {
            int i = (u & 2) ? ib : ia;
            int j = (u & 1) ? jb : ja;
            if ((u & 2) && ib == ia) continue;
            if ((u & 1) && jb == ja) continue;
            float s = (u==0) ? s00 : (u==1) ? s01 : (u==2) ? s10 : s11;
            int ri = i / WS, ci = i % WS, rj = j / WS, cj = j % WS;
            int rpi = (ri - rj + WS - 1)*(2*WS - 1) + (ci - cj + WS - 1);
            s += rpb[rpi*NHd + h];
            if (rid[i] != rid[j]) s -= 100.0f;
            sc[i][j] = s;
        }
    }
    __syncthreads();

    if (tid < Ntok) {
        float mx = -1e30f;
        #pragma unroll 7
        for (int j = 0; j < Ntok; j++) mx = fmaxf(mx, sc[tid][j]);
        float sum = 0.f;
        #pragma unroll 7
        for (int j = 0; j < Ntok; j++) { float e = expf(sc[tid][j] - mx); sc[tid][j] = e; sum += e; }
        float inv = 1.0f / sum;
        #pragma unroll 7
        for (int j = 0; j < Ntok; j++) sc[tid][j] *= inv;
    }
    __syncthreads();

    float* att = g_scratch + OFF_ATT;
    for (int t = tid; t < Ntok*8; t += 128) {
        int i = t >> 3, dq = (t & 7) * 4;
        float ox = 0.f, oy = 0.f, oz = 0.f, ow = 0.f;
        #pragma unroll 7
        for (int j = 0; j < Ntok; j++) {
            float s = sc[i][j];
            float4 v4 = *(const float4*)(&vv[j][dq]);
            ox = fmaf(s, v4.x, ox); oy = fmaf(s, v4.y, oy);
            oz = fmaf(s, v4.z, oz); ow = fmaf(s, v4.w, ow);
        }
        float4 o = {ox, oy, oz, ow};
        *(float4*)(att + (size_t)(m0 + i)*Cch + h*HDim + dq) = o;
    }
}

// ---------------- launch ----------------
extern "C" void kernel_launch(void* const* d_in, const int* in_sizes, int n_in,
                              void* d_out, int out_size) {
    const float* x      = (const float*)d_in[0];
    const float* qkv_w  = (const float*)d_in[1];
    const float* qkv_b  = (const float*)d_in[2];
    const float* proj_w = (const float*)d_in[3];
    const float* proj_b = (const float*)d_in[4];
    const float* rpb    = (const float*)d_in[5];
    const float* n1w    = (const float*)d_in[6];
    const float* n1b    = (const float*)d_in[7];
    const float* n2w    = (const float*)d_in[8];
    const float* n2b    = (const float*)d_in[9];
    const float* fc1w   = (const float*)d_in[10];
    const float* fc1b   = (const float*)d_in[11];
    const float* fc2w   = (const float*)d_in[12];
    const float* fc2b   = (const float*)d_in[13];
    float* out = (float*)d_out;

    tin_kernel<<<dim3(12, 56, 32), 256>>>(x);
    ln_kernel<<<Mrows, 128>>>(OFF_XRAW, n1w, n1b, OFF_XLN);
    tgemm_kernel<<<dim3(1152/128, Mrows/128), 256>>>(OFF_XLN, qkv_w, qkv_b, -1, OFF_QKV,
                                                     Mrows, 1152, Cch, EPI_BIAS);
    attn_kernel<<<NWTOT * NHd, 128>>>(rpb);
    tgemm_kernel<<<dim3(384/128, Mrows/128), 256>>>(OFF_ATT, proj_w, proj_b, (long long)OFF_XRAW,
                                                    OFF_Y, Mrows, Cch, Cch, EPI_RES);
    ln_kernel<<<Mrows, 128>>>(OFF_Y, n2w, n2b, OFF_YLN);
    tgemm_kernel<<<dim3(1536/128, Mrows/128), 256>>>(OFF_YLN, fc1w, fc1b, -1, OFF_H,
                                                     Mrows, HIDd, Cch, EPI_GELU);
    tgemm_kernel<<<dim3(384/128, Mrows/128), 256>>>(OFF_H, fc2w, fc2b, (long long)OFF_Y,
                                                    OFF_FIN, Mrows, Cch, HIDd, EPI_RES);
    tout_kernel<<<dim3(12, 56, 32), 256>>>(out);
}

// round 4
// speedup vs baseline: 2.5673x; 1.1330x over previous
#include <cuda_runtime.h>
#include <math.h>
#include <stdint.h>

// ---------------- problem constants ----------------
#define Bsz   32
#define Cch   384
#define Hh    56
#define Wwid  56
#define WS    7
#define SSH   3
#define NHd   12
#define Ntok  49
#define HDim  32
#define HIDd  1536
#define NWTOT 2048
#define Mrows (NWTOT*Ntok)         // 100352
#define SCALE 0.17677669529663687f

// ---------------- scratch ----------------
constexpr size_t OFF_XRAW = 0;
constexpr size_t OFF_XLN  = OFF_XRAW + (size_t)Mrows*Cch;
constexpr size_t OFF_QKV  = OFF_XLN  + (size_t)Mrows*Cch;
constexpr size_t OFF_ATT  = OFF_QKV  + (size_t)Mrows*(3*Cch);
constexpr size_t OFF_Y    = OFF_ATT  + (size_t)Mrows*Cch;
constexpr size_t OFF_YLN  = OFF_Y    + (size_t)Mrows*Cch;
constexpr size_t OFF_H    = OFF_YLN  + (size_t)Mrows*Cch;
constexpr size_t OFF_FIN  = OFF_H    + (size_t)Mrows*HIDd;
constexpr size_t SCRATCH_FLOATS = OFF_FIN + (size_t)Mrows*Cch;

__device__ float g_scratch[SCRATCH_FLOATS];

// ---------------- helpers ----------------
__device__ __forceinline__ int region(int p) {
    return p < (Hh - WS) ? 0 : (p < (Hh - SSH) ? 1 : 2);
}
__device__ __forceinline__ float gelu_exact(float v) {
    return 0.5f * v * (1.0f + erff(v * 0.70710678118654752f));
}
__device__ __forceinline__ void mma_tf32(float c[4], const uint32_t a[4], const uint32_t b[2]) {
    asm volatile(
        "mma.sync.aligned.m16n8k8.row.col.f32.tf32.tf32.f32 "
        "{%0,%1,%2,%3}, {%4,%5,%6,%7}, {%8,%9}, {%0,%1,%2,%3};\n"
        : "+f"(c[0]), "+f"(c[1]), "+f"(c[2]), "+f"(c[3])
        : "r"(a[0]), "r"(a[1]), "r"(a[2]), "r"(a[3]), "r"(b[0]), "r"(b[1]));
}
__device__ __forceinline__ void cpa16(uint32_t dst, const float* src) {
    asm volatile("cp.async.cg.shared.global [%0], [%1], 16;" :: "r"(dst), "l"(src));
}
__device__ __forceinline__ void cpa_commit() {
    asm volatile("cp.async.commit_group;" ::: "memory");
}
template <int N>
__device__ __forceinline__ void cpa_wait() {
    asm volatile("cp.async.wait_group %0;" :: "n"(N) : "memory");
}
// round fp32 bits to tf32 (rne): add half-ulp of the 13 truncated bits
__device__ __forceinline__ uint32_t rtf(float f) {
    return __float_as_uint(f) + 0x1000u;
}

// ---------------- transpose-in ----------------
__global__ void __launch_bounds__(256) tin_kernel(const float* __restrict__ x) {
    int ct = blockIdx.x, hh = blockIdx.y, b = blockIdx.z;
    __shared__ float tile[32][57];
    int h0 = hh + SSH; if (h0 >= Hh) h0 -= Hh;
    for (int idx = threadIdx.x; idx < 32*56; idx += 256) {
        int i = idx / 56, ws = idx - i*56;
        tile[i][ws] = x[((size_t)(b*Cch + ct*32 + i))*(Hh*Wwid) + h0*Wwid + ws];
    }
    __syncthreads();
    int wh = hh / WS, r = hh % WS;
    for (int idx = threadIdx.x; idx < 56*32; idx += 256) {
        int t = idx >> 5, i = idx & 31;
        int wsrc = t + SSH; if (wsrc >= Wwid) wsrc -= Wwid;
        int ww = t / WS, c = t % WS;
        int m = (((b*8 + wh)*8 + ww)*Ntok) + r*WS + c;
        g_scratch[OFF_XRAW + (size_t)m*Cch + ct*32 + i] = tile[i][wsrc];
    }
}

// ---------------- transpose-out ----------------
__global__ void __launch_bounds__(256) tout_kernel(float* __restrict__ out) {
    int ct = blockIdx.x, h0 = blockIdx.y, b = blockIdx.z;
    __shared__ float tile[32][57];
    int hh = h0 - SSH; if (hh < 0) hh += Hh;
    int wh = hh / WS, r = hh % WS;
    for (int idx = threadIdx.x; idx < 56*32; idx += 256) {
        int t = idx >> 5, i = idx & 31;
        int ww = t / WS, c = t % WS;
        int m = (((b*8 + wh)*8 + ww)*Ntok) + r*WS + c;
        int w0 = t + SSH; if (w0 >= Wwid) w0 -= Wwid;
        tile[i][w0] = g_scratch[OFF_FIN + (size_t)m*Cch + ct*32 + i];
    }
    __syncthreads();
    for (int idx = threadIdx.x; idx < 32*56; idx += 256) {
        int i = idx / 56, w0 = idx - i*56;
        out[((size_t)(b*Cch + ct*32 + i))*(Hh*Wwid) + h0*Wwid + w0] = tile[i][w0];
    }
}

// ---------------- layernorm ----------------
__global__ void __launch_bounds__(128) ln_kernel(size_t Xoff, const float* __restrict__ gam,
                                                 const float* __restrict__ bet, size_t Yoff) {
    int row = blockIdx.x;
    const float* x = g_scratch + Xoff + (size_t)row*Cch;
    float*       y = g_scratch + Yoff + (size_t)row*Cch;
    int c = threadIdx.x;
    float v0 = x[c], v1 = x[c+128], v2 = x[c+256];
    float s = v0+v1+v2, s2 = v0*v0 + v1*v1 + v2*v2;
    #pragma unroll
    for (int o = 16; o; o >>= 1) {
        s  += __shfl_xor_sync(0xffffffffu, s,  o);
        s2 += __shfl_xor_sync(0xffffffffu, s2, o);
    }
    __shared__ float rs[4], rs2[4];
    int wid = c >> 5;
    if ((c & 31) == 0) { rs[wid] = s; rs2[wid] = s2; }
    __syncthreads();
    s  = rs[0]+rs[1]+rs[2]+rs[3];
    s2 = rs2[0]+rs2[1]+rs2[2]+rs2[3];
    float mean = s * (1.0f/Cch);
    float var  = s2 * (1.0f/Cch) - mean*mean;
    float inv  = rsqrtf(var + 1e-5f);
    y[c]     = (v0-mean)*inv*gam[c]     + bet[c];
    y[c+128] = (v1-mean)*inv*gam[c+128] + bet[c+128];
    y[c+256] = (v2-mean)*inv*gam[c+256] + bet[c+256];
}

// ---------------- TF32 GEMM: 128x128 block, BK=16, 4-stage cp.async pipeline
#define EPI_BIAS 0
#define EPI_RES  1
#define EPI_GELU 2

#define AST 20    // As row stride (floats) — conflict-free fragment loads
#define BST 136   // Bs row stride (floats)
#define STAGES 4
#define A_STG (128*AST)
#define B_STG (16*BST)
constexpr int SMEM_GEMM_BYTES = STAGES * (A_STG + B_STG) * 4;   // 75776

__global__ void __launch_bounds__(256, 2) tgemm_kernel(
    size_t Aoff, const float* __restrict__ B, const float* __restrict__ bias,
    long long resoff, size_t Coff, int M, int N, int K, int epi)
{
    extern __shared__ float smem_dyn[];
    float* As = smem_dyn;                     // [STAGES][128*AST]
    float* Bs = smem_dyn + STAGES*A_STG;      // [STAGES][16*BST]
    uint32_t as_sm = (uint32_t)__cvta_generic_to_shared(As);
    uint32_t bs_sm = (uint32_t)__cvta_generic_to_shared(Bs);

    const float* A = g_scratch + Aoff;
    float*       C = g_scratch + Coff;
    int tid = threadIdx.x;
    int warp = tid >> 5, lane = tid & 31;
    int wrow = warp >> 2, wcol = warp & 3;
    int g = lane >> 2, qc = lane & 3;
    int brow = blockIdx.y, bcol = blockIdx.x;

    const float* Ablk = A + (size_t)brow*128*K;
    const float* Bblk = B + bcol*128;

    int arow = tid >> 1;            // 0..127
    int akc  = (tid & 1) * 8;       // 0 / 8
    int bkr  = tid >> 4;            // 0..15
    int bcl  = (tid & 15) * 8;      // 0..120

    int nk = K >> 4;

    // issue loads for tile kt into stage s
    auto load_tile = [&](int s, int kt) {
        const float* Ap = Ablk + (size_t)arow*K + kt*16 + akc;
        uint32_t ad = as_sm + (uint32_t)(s*A_STG + arow*AST + akc)*4;
        cpa16(ad,      Ap);
        cpa16(ad + 16, Ap + 4);
        const float* Bp = Bblk + (size_t)(kt*16 + bkr)*N + bcl;
        uint32_t bd = bs_sm + (uint32_t)(s*B_STG + bkr*BST + bcl)*4;
        cpa16(bd,      Bp);
        cpa16(bd + 16, Bp + 4);
    };

    float acc[4][4][4];
    #pragma unroll
    for (int i = 0; i < 4; i++)
        #pragma unroll
        for (int j = 0; j < 4; j++)
            #pragma unroll
            for (int r = 0; r < 4; r++) acc[i][j][r] = 0.f;

    // prologue: tiles 0..2 into stages 0..2
    load_tile(0, 0); cpa_commit();
    load_tile(1, 1); cpa_commit();
    load_tile(2, 2); cpa_commit();
    cpa_wait<2>();            // tile 0 resident
    __syncthreads();

    int stage = 0;
    for (int kt = 0; kt < nk; kt++) {
        if (kt + 3 < nk) {
            int s = stage + 3 >= STAGES ? stage + 3 - STAGES : stage + 3;
            load_tile(s, kt + 3);
        }
        cpa_commit();         // possibly empty group — keeps wait count uniform

        const float* Asb = As + stage*A_STG;
        const float* Bsb = Bs + stage*B_STG;
        #pragma unroll
        for (int sub = 0; sub < 2; sub++) {
            uint32_t af[4][4];
            #pragma unroll
            for (int i = 0; i < 4; i++) {
                int r = wrow*64 + i*16 + g;
                int kb = sub*8 + qc;
                af[i][0] = rtf(Asb[r*AST + kb]);
                af[i][1] = rtf(Asb[(r+8)*AST + kb]);
                af[i][2] = rtf(Asb[r*AST + kb + 4]);
                af[i][3] = rtf(Asb[(r+8)*AST + kb + 4]);
            }
            uint32_t bf[4][2];
            #pragma unroll
            for (int j = 0; j < 4; j++) {
                int cidx = wcol*32 + j*8 + g;
                bf[j][0] = rtf(Bsb[(sub*8 + qc)*BST + cidx]);
                bf[j][1] = rtf(Bsb[(sub*8 + qc + 4)*BST + cidx]);
            }
            #pragma unroll
            for (int i = 0; i < 4; i++)
                #pragma unroll
                for (int j = 0; j < 4; j++)
                    mma_tf32(acc[i][j], af[i], bf[j]);
        }
        cpa_wait<2>();        // tile kt+1 resident; kt+2/kt+3 may be in flight
        __syncthreads();
        stage = stage + 1 == STAGES ? 0 : stage + 1;
    }

    const float* res = (resoff >= 0) ? (g_scratch + (size_t)resoff) : nullptr;
    #pragma unroll
    for (int i = 0; i < 4; i++) {
        int r0 = brow*128 + wrow*64 + i*16 + g;
        #pragma unroll
        for (int j = 0; j < 4; j++) {
            int cb = bcol*128 + wcol*32 + j*8 + qc*2;
            float bx = bias[cb], by = bias[cb+1];
            #pragma unroll
            for (int half = 0; half < 2; half++) {
                int row = r0 + half*8;
                float vx = acc[i][j][half*2]   + bx;
                float vy = acc[i][j][half*2+1] + by;
                if (epi == EPI_GELU) { vx = gelu_exact(vx); vy = gelu_exact(vy); }
                else if (epi == EPI_RES) {
                    float2 rr = *(const float2*)(res + (size_t)row*N + cb);
                    vx += rr.x; vy += rr.y;
                }
                float2 o = {vx, vy};
                *(float2*)(C + (size_t)row*N + cb) = o;
            }
        }
    }
}

// ---------------- windowed attention (round-3 version) ----------------
__global__ void __launch_bounds__(128) attn_kernel(const float* __restrict__ rpb) {
    int blk = blockIdx.x;
    int h = blk % NHd;
    int w = blk / NHd;
    int ww = w & 7, wh = (w >> 3) & 7;
    int m0 = w * Ntok;
    __shared__ float q[Ntok][36], kk[Ntok][36], vv[Ntok][36];
    __shared__ float sc[Ntok][50];
    __shared__ int   rid[Ntok];
    int tid = threadIdx.x;

    const float* qkv = g_scratch + OFF_QKV;
    for (int idx = tid; idx < Ntok*8; idx += 128) {
        int i = idx >> 3, dq = (idx & 7) * 4;
        size_t base = (size_t)(m0 + i)*(3*Cch) + h*HDim + dq;
        float4 qa = *(const float4*)(qkv + base);
        float4 ka = *(const float4*)(qkv + base + Cch);
        float4 va = *(const float4*)(qkv + base + 2*Cch);
        qa.x *= SCALE; qa.y *= SCALE; qa.z *= SCALE; qa.w *= SCALE;
        *(float4*)(&q [i][dq]) = qa;
        *(float4*)(&kk[i][dq]) = ka;
        *(float4*)(&vv[i][dq]) = va;
    }
    if (tid < Ntok) {
        int r = tid / WS, c = tid % WS;
        rid[tid] = region(wh*WS + r)*3 + region(ww*WS + c);
    }
    __syncthreads();

    for (int t = tid; t < 625; t += 128) {
        int i0 = t / 25, j0 = t % 25;
        int ia = i0*2, ja = j0*2;
        int ib = ia + 1 < Ntok ? ia + 1 : ia;
        int jb = ja + 1 < Ntok ? ja + 1 : ja;
        float s00 = 0.f, s01 = 0.f, s10 = 0.f, s11 = 0.f;
        #pragma unroll
        for (int d = 0; d < HDim; d += 4) {
            float4 qa = *(const float4*)(&q[ia][d]);
            float4 qb = *(const float4*)(&q[ib][d]);
            float4 ka = *(const float4*)(&kk[ja][d]);
            float4 kb = *(const float4*)(&kk[jb][d]);
            s00 = fmaf(qa.x,ka.x, fmaf(qa.y,ka.y, fmaf(qa.z,ka.z, fmaf(qa.w,ka.w, s00))));
            s01 = fmaf(qa.x,kb.x, fmaf(qa.y,kb.y, fmaf(qa.z,kb.z, fmaf(qa.w,kb.w, s01))));
            s10 = fmaf(qb.x,ka.x, fmaf(qb.y,ka.y, fmaf(qb.z,ka.z, fmaf(qb.w,ka.w, s10))));
            s11 = fmaf(qb.x,kb.x, fmaf(qb.y,kb.y, fmaf(qb.z,kb.z, fmaf(qb.w,kb.w, s11))));
        }
        #pragma unroll
        for (int u = 0; u < 4; u++) {
            int i = (u & 2) ? ib : ia;
            int j = (u & 1) ? jb : ja;
            if ((u & 2) && ib == ia) continue;
            if ((u & 1) && jb == ja) continue;
            float s = (u==0) ? s00 : (u==1) ? s01 : (u==2) ? s10 : s11;
            int ri = i / WS, ci = i % WS, rj = j / WS, cj = j % WS;
            int rpi = (ri - rj + WS - 1)*(2*WS - 1) + (ci - cj + WS - 1);
            s += rpb[rpi*NHd + h];
            if (rid[i] != rid[j]) s -= 100.0f;
            sc[i][j] = s;
        }
    }
    __syncthreads();

    if (tid < Ntok) {
        float mx = -1e30f;
        #pragma unroll 7
        for (int j = 0; j < Ntok; j++) mx = fmaxf(mx, sc[tid][j]);
        float sum = 0.f;
        #pragma unroll 7
        for (int j = 0; j < Ntok; j++) { float e = expf(sc[tid][j] - mx); sc[tid][j] = e; sum += e; }
        float inv = 1.0f / sum;
        #pragma unroll 7
        for (int j = 0; j < Ntok; j++) sc[tid][j] *= inv;
    }
    __syncthreads();

    float* att = g_scratch + OFF_ATT;
    for (int t = tid; t < Ntok*8; t += 128) {
        int i = t >> 3, dq = (t & 7) * 4;
        float ox = 0.f, oy = 0.f, oz = 0.f, ow = 0.f;
        #pragma unroll 7
        for (int j = 0; j < Ntok; j++) {
            float s = sc[i][j];
            float4 v4 = *(const float4*)(&vv[j][dq]);
            ox = fmaf(s, v4.x, ox); oy = fmaf(s, v4.y, oy);
            oz = fmaf(s, v4.z, oz); ow = fmaf(s, v4.w, ow);
        }
        float4 o = {ox, oy, oz, ow};
        *(float4*)(att + (size_t)(m0 + i)*Cch + h*HDim + dq) = o;
    }
}

// ---------------- launch ----------------
extern "C" void kernel_launch(void* const* d_in, const int* in_sizes, int n_in,
                              void* d_out, int out_size) {
    const float* x      = (const float*)d_in[0];
    const float* qkv_w  = (const float*)d_in[1];
    const float* qkv_b  = (const float*)d_in[2];
    const float* proj_w = (const float*)d_in[3];
    const float* proj_b = (const float*)d_in[4];
    const float* rpb    = (const float*)d_in[5];
    const float* n1w    = (const float*)d_in[6];
    const float* n1b    = (const float*)d_in[7];
    const float* n2w    = (const float*)d_in[8];
    const float* n2b    = (const float*)d_in[9];
    const float* fc1w   = (const float*)d_in[10];
    const float* fc1b   = (const float*)d_in[11];
    const float* fc2w   = (const float*)d_in[12];
    const float* fc2b   = (const float*)d_in[13];
    float* out = (float*)d_out;

    cudaFuncSetAttribute(tgemm_kernel, cudaFuncAttributeMaxDynamicSharedMemorySize,
                         SMEM_GEMM_BYTES);

    tin_kernel<<<dim3(12, 56, 32), 256>>>(x);
    ln_kernel<<<Mrows, 128>>>(OFF_XRAW, n1w, n1b, OFF_XLN);
    tgemm_kernel<<<dim3(1152/128, Mrows/128), 256, SMEM_GEMM_BYTES>>>(
        OFF_XLN, qkv_w, qkv_b, -1, OFF_QKV, Mrows, 1152, Cch, EPI_BIAS);
    attn_kernel<<<NWTOT * NHd, 128>>>(rpb);
    tgemm_kernel<<<dim3(384/128, Mrows/128), 256, SMEM_GEMM_BYTES>>>(
        OFF_ATT, proj_w, proj_b, (long long)OFF_XRAW, OFF_Y, Mrows, Cch, Cch, EPI_RES);
    ln_kernel<<<Mrows, 128>>>(OFF_Y, n2w, n2b, OFF_YLN);
    tgemm_kernel<<<dim3(1536/128, Mrows/128), 256, SMEM_GEMM_BYTES>>>(
        OFF_YLN, fc1w, fc1b, -1, OFF_H, Mrows, HIDd, Cch, EPI_GELU);
    tgemm_kernel<<<dim3(384/128, Mrows/128), 256, SMEM_GEMM_BYTES>>>(
        OFF_H, fc2w, fc2b, (long long)OFF_Y, OFF_FIN, Mrows, Cch, HIDd, EPI_RES);
    tout_kernel<<<dim3(12, 56, 32), 256>>>(out);
}

// round 7
// speedup vs baseline: 2.6398x; 1.0283x over previous
#include <cuda_runtime.h>
#include <math.h>
#include <stdint.h>

// ---------------- problem constants ----------------
#define Bsz   32
#define Cch   384
#define Hh    56
#define Wwid  56
#define WS    7
#define SSH   3
#define NHd   12
#define Ntok  49
#define HDim  32
#define HIDd  1536
#define NWTOT 2048
#define Mrows (NWTOT*Ntok)         // 100352
#define SCALE 0.17677669529663687f

// ---------------- scratch ----------------
constexpr size_t OFF_XRAW = 0;
constexpr size_t OFF_XLN  = OFF_XRAW + (size_t)Mrows*Cch;
constexpr size_t OFF_QKV  = OFF_XLN  + (size_t)Mrows*Cch;
constexpr size_t OFF_ATT  = OFF_QKV  + (size_t)Mrows*(3*Cch);
constexpr size_t OFF_Y    = OFF_ATT  + (size_t)Mrows*Cch;
constexpr size_t OFF_YLN  = OFF_Y    + (size_t)Mrows*Cch;
constexpr size_t OFF_H    = OFF_YLN  + (size_t)Mrows*Cch;
constexpr size_t OFF_FIN  = OFF_H    + (size_t)Mrows*HIDd;
// bumped weight copies (same [K][N] layout as inputs)
constexpr size_t OFF_WQKV = OFF_FIN  + (size_t)Mrows*Cch;     // [384][1152]
constexpr size_t OFF_WPRJ = OFF_WQKV + (size_t)384*1152;      // [384][384]
constexpr size_t OFF_WFC1 = OFF_WPRJ + (size_t)384*384;       // [384][1536]
constexpr size_t OFF_WFC2 = OFF_WFC1 + (size_t)384*1536;      // [1536][384]
constexpr size_t SCRATCH_FLOATS = OFF_WFC2 + (size_t)1536*384;

__device__ float g_scratch[SCRATCH_FLOATS];

// ---------------- helpers ----------------
__device__ __forceinline__ int region(int p) {
    return p < (Hh - WS) ? 0 : (p < (Hh - SSH) ? 1 : 2);
}
__device__ __forceinline__ float gelu_exact(float v) {
    return 0.5f * v * (1.0f + erff(v * 0.70710678118654752f));
}
// pre-bias fp32 so hardware tf32 truncation becomes round-to-nearest
__device__ __forceinline__ float bump(float f) {
    return __uint_as_float(__float_as_uint(f) + 0x1000u);
}
__device__ __forceinline__ void mma_tf32(float c[4], const uint32_t a[4], const uint32_t b[2]) {
    asm volatile(
        "mma.sync.aligned.m16n8k8.row.col.f32.tf32.tf32.f32 "
        "{%0,%1,%2,%3}, {%4,%5,%6,%7}, {%8,%9}, {%0,%1,%2,%3};\n"
        : "+f"(c[0]), "+f"(c[1]), "+f"(c[2]), "+f"(c[3])
        : "r"(a[0]), "r"(a[1]), "r"(a[2]), "r"(a[3]), "r"(b[0]), "r"(b[1]));
}
__device__ __forceinline__ void cpa16(uint32_t dst, const float* src) {
    asm volatile("cp.async.cg.shared.global [%0], [%1], 16;" :: "r"(dst), "l"(src));
}
__device__ __forceinline__ void cpa_commit() {
    asm volatile("cp.async.commit_group;" ::: "memory");
}
template <int N>
__device__ __forceinline__ void cpa_wait() {
    asm volatile("cp.async.wait_group %0;" :: "n"(N) : "memory");
}

// ---------------- transpose-in ----------------
__global__ void __launch_bounds__(256) tin_kernel(const float* __restrict__ x) {
    int ct = blockIdx.x, hh = blockIdx.y, b = blockIdx.z;
    __shared__ float tile[32][57];
    int h0 = hh + SSH; if (h0 >= Hh) h0 -= Hh;
    for (int idx = threadIdx.x; idx < 32*56; idx += 256) {
        int i = idx / 56, ws = idx - i*56;
        tile[i][ws] = x[((size_t)(b*Cch + ct*32 + i))*(Hh*Wwid) + h0*Wwid + ws];
    }
    __syncthreads();
    int wh = hh / WS, r = hh % WS;
    for (int idx = threadIdx.x; idx < 56*32; idx += 256) {
        int t = idx >> 5, i = idx & 31;
        int wsrc = t + SSH; if (wsrc >= Wwid) wsrc -= Wwid;
        int ww = t / WS, c = t % WS;
        int m = (((b*8 + wh)*8 + ww)*Ntok) + r*WS + c;
        g_scratch[OFF_XRAW + (size_t)m*Cch + ct*32 + i] = tile[i][wsrc];
    }
}

// ---------------- transpose-out ----------------
__global__ void __launch_bounds__(256) tout_kernel(float* __restrict__ out) {
    int ct = blockIdx.x, h0 = blockIdx.y, b = blockIdx.z;
    __shared__ float tile[32][57];
    int hh = h0 - SSH; if (hh < 0) hh += Hh;
    int wh = hh / WS, r = hh % WS;
    for (int idx = threadIdx.x; idx < 56*32; idx += 256) {
        int t = idx >> 5, i = idx & 31;
        int ww = t / WS, c = t % WS;
        int m = (((b*8 + wh)*8 + ww)*Ntok) + r*WS + c;
        int w0 = t + SSH; if (w0 >= Wwid) w0 -= Wwid;
        tile[i][w0] = g_scratch[OFF_FIN + (size_t)m*Cch + ct*32 + i];
    }
    __syncthreads();
    for (int idx = threadIdx.x; idx < 32*56; idx += 256) {
        int i = idx / 56, w0 = idx - i*56;
        out[((size_t)(b*Cch + ct*32 + i))*(Hh*Wwid) + h0*Wwid + w0] = tile[i][w0];
    }
}

// ---------------- bumped weight copy ----------------
__global__ void __launch_bounds__(256) wcopy_kernel(const float* __restrict__ src,
                                                    int n, size_t off) {
    int i = blockIdx.x*256 + threadIdx.x;
    if (i < n) g_scratch[off + i] = bump(src[i]);
}

// ---------------- layernorm (bumped output — feeds GEMMs only) --------------
__global__ void __launch_bounds__(128) ln_kernel(size_t Xoff, const float* __restrict__ gam,
                                                 const float* __restrict__ bet, size_t Yoff) {
    int row = blockIdx.x;
    const float* x = g_scratch + Xoff + (size_t)row*Cch;
    float*       y = g_scratch + Yoff + (size_t)row*Cch;
    int c = threadIdx.x;
    float v0 = x[c], v1 = x[c+128], v2 = x[c+256];
    float s = v0+v1+v2, s2 = v0*v0 + v1*v1 + v2*v2;
    #pragma unroll
    for (int o = 16; o; o >>= 1) {
        s  += __shfl_xor_sync(0xffffffffu, s,  o);
        s2 += __shfl_xor_sync(0xffffffffu, s2, o);
    }
    __shared__ float rs[4], rs2[4];
    int wid = c >> 5;
    if ((c & 31) == 0) { rs[wid] = s; rs2[wid] = s2; }
    __syncthreads();
    s  = rs[0]+rs[1]+rs[2]+rs[3];
    s2 = rs2[0]+rs2[1]+rs2[2]+rs2[3];
    float mean = s * (1.0f/Cch);
    float var  = s2 * (1.0f/Cch) - mean*mean;
    float inv  = rsqrtf(var + 1e-5f);
    y[c]     = bump((v0-mean)*inv*gam[c]     + bet[c]);
    y[c+128] = bump((v1-mean)*inv*gam[c+128] + bet[c+128]);
    y[c+256] = bump((v2-mean)*inv*gam[c+256] + bet[c+256]);
}

// ---------------- TF32 GEMM: 128x128 block, BK=16, 4-stage cp.async ----------
// Inputs pre-bumped; inner loop = pure LDS + MMA. A fragments via LDS.64 with
// k-slot relabeling {2qc, 2qc+1}; B smem rows permuted at staging to match.
#define EPI_BIAS 0
#define EPI_RES  1
#define EPI_GELU 2

#define AST 20
#define BST 136
#define STAGES 4
#define A_STG (128*AST)
#define B_STG (16*BST)
constexpr int SMEM_GEMM_BYTES = STAGES * (A_STG + B_STG) * 4;   // 75776

__global__ void __launch_bounds__(256, 2) tgemm_kernel(
    size_t Aoff, size_t Boff, const float* __restrict__ bias,
    long long resoff, size_t Coff, int M, int N, int K, int epi)
{
    extern __shared__ float smem_dyn[];
    float* As = smem_dyn;
    float* Bs = smem_dyn + STAGES*A_STG;
    uint32_t as_sm = (uint32_t)__cvta_generic_to_shared(As);
    uint32_t bs_sm = (uint32_t)__cvta_generic_to_shared(Bs);

    const float* A = g_scratch + Aoff;
    const float* B = g_scratch + Boff;
    float*       C = g_scratch + Coff;
    int tid = threadIdx.x;
    int warp = tid >> 5, lane = tid & 31;
    int wrow = warp >> 2, wcol = warp & 3;
    int g = lane >> 2, qc = lane & 3;
    int brow = blockIdx.y, bcol = blockIdx.x;

    const float* Ablk = A + (size_t)brow*128*K;
    const float* Bblk = B + bcol*128;

    int arow = tid >> 1;            // 0..127
    int akc  = (tid & 1) * 8;       // 0 / 8
    int bkr  = tid >> 4;            // smem row 0..15
    int bcl  = (tid & 15) * 8;      // 0..120
    // permuted global k for this smem row: row w holds k = (w<4 ? 2w : 2(w-4)+1)
    int w8  = bkr & 7;
    int bgk = (bkr & 8) + ((w8 < 4) ? (2*w8) : (2*(w8-4)+1));

    auto load_tile = [&](int s, int kt) {
        const float* Ap = Ablk + (size_t)arow*K + kt*16 + akc;
        uint32_t ad = as_sm + (uint32_t)(s*A_STG + arow*AST + akc)*4;
        cpa16(ad,      Ap);
        cpa16(ad + 16, Ap + 4);
        const float* Bp = Bblk + (size_t)(kt*16 + bgk)*N + bcl;
        uint32_t bd = bs_sm + (uint32_t)(s*B_STG + bkr*BST + bcl)*4;
        cpa16(bd,      Bp);
        cpa16(bd + 16, Bp + 4);
    };

    float acc[4][4][4];
    #pragma unroll
    for (int i = 0; i < 4; i++)
        #pragma unroll
        for (int j = 0; j < 4; j++)
            #pragma unroll
            for (int r = 0; r < 4; r++) acc[i][j][r] = 0.f;

    int nk = K >> 4;
    load_tile(0, 0); cpa_commit();
    load_tile(1, 1); cpa_commit();
    load_tile(2, 2); cpa_commit();
    cpa_wait<2>();
    __syncthreads();

    int stage = 0;
    for (int kt = 0; kt < nk; kt++) {
        if (kt + 3 < nk) {
            int s = stage + 3 >= STAGES ? stage + 3 - STAGES : stage + 3;
            load_tile(s, kt + 3);
        }
        cpa_commit();

        const float* Asb = As + stage*A_STG;
        const float* Bsb = Bs + stage*B_STG;
        #pragma unroll
        for (int sub = 0; sub < 2; sub++) {
            int kb2 = sub*8 + 2*qc;
            uint32_t af[4][4];
            #pragma unroll
            for (int i = 0; i < 4; i++) {
                int r = wrow*64 + i*16 + g;
                uint2 p0 = *(const uint2*)(Asb + r*AST + kb2);        // {a0, a2}
                uint2 p1 = *(const uint2*)(Asb + (r+8)*AST + kb2);    // {a1, a3}
                af[i][0] = p0.x; af[i][1] = p1.x; af[i][2] = p0.y; af[i][3] = p1.y;
            }
            uint32_t bf[4][2];
            #pragma unroll
            for (int j = 0; j < 4; j++) {
                int cidx = wcol*32 + j*8 + g;
                bf[j][0] = __float_as_uint(Bsb[(sub*8 + qc)*BST + cidx]);
                bf[j][1] = __float_as_uint(Bsb[(sub*8 + qc + 4)*BST + cidx]);
            }
            #pragma unroll
            for (int i = 0; i < 4; i++)
                #pragma unroll
                for (int j = 0; j < 4; j++)
                    mma_tf32(acc[i][j], af[i], bf[j]);
        }
        cpa_wait<2>();
        __syncthreads();
        stage = stage + 1 == STAGES ? 0 : stage + 1;
    }

    const float* res = (resoff >= 0) ? (g_scratch + (size_t)resoff) : nullptr;
    #pragma unroll
    for (int i = 0; i < 4; i++) {
        int r0 = brow*128 + wrow*64 + i*16 + g;
        #pragma unroll
        for (int j = 0; j < 4; j++) {
            int cb = bcol*128 + wcol*32 + j*8 + qc*2;
            float bx = bias[cb], by = bias[cb+1];
            #pragma unroll
            for (int half = 0; half < 2; half++) {
                int row = r0 + half*8;
                float vx = acc[i][j][half*2]   + bx;
                float vy = acc[i][j][half*2+1] + by;
                if (epi == EPI_GELU) { vx = bump(gelu_exact(vx)); vy = bump(gelu_exact(vy)); }
                else if (epi == EPI_RES) {
                    float2 rr = *(const float2*)(res + (size_t)row*N + cb);
                    vx += rr.x; vy += rr.y;
                }
                float2 o = {vx, vy};
                *(float2*)(C + (size_t)row*N + cb) = o;
            }
        }
    }
}

// ---------------- windowed attention — conflict-reduced blocking -------------
__global__ void __launch_bounds__(128) attn_kernel(const float* __restrict__ rpb) {
    int blk = blockIdx.x;
    int h = blk % NHd;
    int w = blk / NHd;
    int ww = w & 7, wh = (w >> 3) & 7;
    int m0 = w * Ntok;
    __shared__ float q[Ntok][36], kk[Ntok][36], vv[Ntok][36];
    __shared__ float sc[Ntok][52];
    __shared__ int   rid[Ntok];
    int tid = threadIdx.x;

    const float* qkv = g_scratch + OFF_QKV;
    for (int idx = tid; idx < Ntok*8; idx += 128) {
        int i = idx >> 3, dq = (idx & 7) * 4;
        size_t base = (size_t)(m0 + i)*(3*Cch) + h*HDim + dq;
        float4 qa = *(const float4*)(qkv + base);
        float4 ka = *(const float4*)(qkv + base + Cch);
        float4 va = *(const float4*)(qkv + base + 2*Cch);
        qa.x *= SCALE; qa.y *= SCALE; qa.z *= SCALE; qa.w *= SCALE;
        *(float4*)(&q [i][dq]) = qa;
        *(float4*)(&kk[i][dq]) = ka;
        *(float4*)(&vv[i][dq]) = va;
    }
    if (tid < Ntok) {
        int r = tid / WS, c = tid % WS;
        rid[tid] = region(wh*WS + r)*3 + region(ww*WS + c);
    }
    __syncthreads();

    // QK^T: 4x4 blocks with interleaved rows {b, b+13, b+26, b+39}
    for (int t = tid; t < 169; t += 128) {
        int ib = t / 13, jb = t % 13;
        int ir[4] = { ib, ib+13, ib+26, (ib+39 < Ntok) ? ib+39 : 48 };
        int jr[4] = { jb, jb+13, jb+26, (jb+39 < Ntok) ? jb+39 : 48 };
        float a[4][4];
        #pragma unroll
        for (int r = 0; r < 4; r++)
            #pragma unroll
            for (int s = 0; s < 4; s++) a[r][s] = 0.f;
        #pragma unroll
        for (int d = 0; d < HDim; d += 4) {
            float4 qv[4], kv[4];
            #pragma unroll
            for (int r = 0; r < 4; r++) qv[r] = *(const float4*)(&q[ir[r]][d]);
            #pragma unroll
            for (int s = 0; s < 4; s++) kv[s] = *(const float4*)(&kk[jr[s]][d]);
            #pragma unroll
            for (int r = 0; r < 4; r++)
                #pragma unroll
                for (int s = 0; s < 4; s++)
                    a[r][s] = fmaf(qv[r].x, kv[s].x, fmaf(qv[r].y, kv[s].y,
                              fmaf(qv[r].z, kv[s].z, fmaf(qv[r].w, kv[s].w, a[r][s]))));
        }
        #pragma unroll
        for (int r = 0; r < 4; r++) {
            if (r == 3 && ib + 39 >= Ntok) continue;
            int i = ir[r];
            int ri = i / WS, ci = i % WS, rdi = rid[i];
            #pragma unroll
            for (int s = 0; s < 4; s++) {
                if (s == 3 && jb + 39 >= Ntok) continue;
                int j = jr[s];
                int rj = j / WS, cj = j % WS;
                int rpi = (ri - rj + WS - 1)*(2*WS - 1) + (ci - cj + WS - 1);
                float v = a[r][s] + rpb[rpi*NHd + h];
                if (rdi != rid[j]) v -= 100.0f;
                sc[i][j] = v;
            }
        }
    }
    __syncthreads();

    // softmax: 2 threads per row, shfl combine
    {
        int i = tid >> 1, p = tid & 1;
        bool act = i < Ntok;
        int ic = act ? i : 48;
        float mx = -1e30f;
        for (int j = p; j < Ntok; j += 2) mx = fmaxf(mx, sc[ic][j]);
        mx = fmaxf(mx, __shfl_xor_sync(0xffffffffu, mx, 1));
        float sum = 0.f;
        for (int j = p; j < Ntok; j += 2) {
            float e = __expf(sc[ic][j] - mx);
            if (act) sc[ic][j] = e;
            sum += e;
        }
        sum += __shfl_xor_sync(0xffffffffu, sum, 1);
        float inv = 1.0f / sum;
        if (act)
            for (int j = p; j < Ntok; j += 2) sc[ic][j] *= inv;
    }
    __syncthreads();

    // AV: task = (row pair, 8-col block); V loads broadcast across lanes
    float* att = g_scratch + OFF_ATT;
    if (tid < 100) {
        int ip = tid >> 2, cb = (tid & 3) * 8;
        int i0 = 2*ip, i1p = 2*ip + 1;
        int i1 = (i1p < Ntok) ? i1p : 48;
        float a0[8], a1[8];
        #pragma unroll
        for (int c = 0; c < 8; c++) { a0[c] = 0.f; a1[c] = 0.f; }
        for (int j = 0; j < Ntok; j++) {
            float s0 = sc[i0][j], s1 = sc[i1][j];
            float4 va = *(const float4*)(&vv[j][cb]);
            float4 vb = *(const float4*)(&vv[j][cb+4]);
            a0[0]=fmaf(s0,va.x,a0[0]); a0[1]=fmaf(s0,va.y,a0[1]);
            a0[2]=fmaf(s0,va.z,a0[2]); a0[3]=fmaf(s0,va.w,a0[3]);
            a0[4]=fmaf(s0,vb.x,a0[4]); a0[5]=fmaf(s0,vb.y,a0[5]);
            a0[6]=fmaf(s0,vb.z,a0[6]); a0[7]=fmaf(s0,vb.w,a0[7]);
            a1[0]=fmaf(s1,va.x,a1[0]); a1[1]=fmaf(s1,va.y,a1[1]);
            a1[2]=fmaf(s1,va.z,a1[2]); a1[3]=fmaf(s1,va.w,a1[3]);
            a1[4]=fmaf(s1,vb.x,a1[4]); a1[5]=fmaf(s1,vb.y,a1[5]);
            a1[6]=fmaf(s1,vb.z,a1[6]); a1[7]=fmaf(s1,vb.w,a1[7]);
        }
        float* o0 = att + (size_t)(m0 + i0)*Cch + h*HDim + cb;
        float4 v0 = {bump(a0[0]), bump(a0[1]), bump(a0[2]), bump(a0[3])};
        float4 v1 = {bump(a0[4]), bump(a0[5]), bump(a0[6]), bump(a0[7])};
        *(float4*)(o0)     = v0;
        *(float4*)(o0 + 4) = v1;
        if (i1p < Ntok) {
            float* o1 = att + (size_t)(m0 + i1p)*Cch + h*HDim + cb;
            float4 w0 = {bump(a1[0]), bump(a1[1]), bump(a1[2]), bump(a1[3])};
            float4 w1 = {bump(a1[4]), bump(a1[5]), bump(a1[6]), bump(a1[7])};
            *(float4*)(o1)     = w0;
            *(float4*)(o1 + 4) = w1;
        }
    }
}

// ---------------- launch ----------------
extern "C" void kernel_launch(void* const* d_in, const int* in_sizes, int n_in,
                              void* d_out, int out_size) {
    const float* x      = (const float*)d_in[0];
    const float* qkv_w  = (const float*)d_in[1];
    const float* qkv_b  = (const float*)d_in[2];
    const float* proj_w = (const float*)d_in[3];
    const float* proj_b = (const float*)d_in[4];
    const float* rpb    = (const float*)d_in[5];
    const float* n1w    = (const float*)d_in[6];
    const float* n1b    = (const float*)d_in[7];
    const float* n2w    = (const float*)d_in[8];
    const float* n2b    = (const float*)d_in[9];
    const float* fc1w   = (const float*)d_in[10];
    const float* fc1b   = (const float*)d_in[11];
    const float* fc2w   = (const float*)d_in[12];
    const float* fc2b   = (const float*)d_in[13];
    float* out = (float*)d_out;

    cudaFuncSetAttribute(tgemm_kernel, cudaFuncAttributeMaxDynamicSharedMemorySize,
                         SMEM_GEMM_BYTES);

    // bumped weight copies (cheap; keeps GEMM inner loop conversion-free)
    wcopy_kernel<<<(384*1152 + 255)/256, 256>>>(qkv_w, 384*1152, OFF_WQKV);
    wcopy_kernel<<<(384*384  + 255)/256, 256>>>(proj_w, 384*384,  OFF_WPRJ);
    wcopy_kernel<<<(384*1536 + 255)/256, 256>>>(fc1w,  384*1536, OFF_WFC1);
    wcopy_kernel<<<(1536*384 + 255)/256, 256>>>(fc2w,  1536*384, OFF_WFC2);

    tin_kernel<<<dim3(12, 56, 32), 256>>>(x);
    ln_kernel<<<Mrows, 128>>>(OFF_XRAW, n1w, n1b, OFF_XLN);
    tgemm_kernel<<<dim3(1152/128, Mrows/128), 256, SMEM_GEMM_BYTES>>>(
        OFF_XLN, OFF_WQKV, qkv_b, -1, OFF_QKV, Mrows, 1152, Cch, EPI_BIAS);
    attn_kernel<<<NWTOT * NHd, 128>>>(rpb);
    tgemm_kernel<<<dim3(384/128, Mrows/128), 256, SMEM_GEMM_BYTES>>>(
        OFF_ATT, OFF_WPRJ, proj_b, (long long)OFF_XRAW, OFF_Y, Mrows, Cch, Cch, EPI_RES);
    ln_kernel<<<Mrows, 128>>>(OFF_Y, n2w, n2b, OFF_YLN);
    tgemm_kernel<<<dim3(1536/128, Mrows/128), 256, SMEM_GEMM_BYTES>>>(
        OFF_YLN, OFF_WFC1, fc1b, -1, OFF_H, Mrows, HIDd, Cch, EPI_GELU);
    tgemm_kernel<<<dim3(384/128, Mrows/128), 256, SMEM_GEMM_BYTES>>>(
        OFF_H, OFF_WFC2, fc2b, (long long)OFF_Y, OFF_FIN, Mrows, Cch, HIDd, EPI_RES);
    tout_kernel<<<dim3(12, 56, 32), 256>>>(out);
}

// round 8
// speedup vs baseline: 3.8188x; 1.4466x over previous
#include <cuda_runtime.h>
#include <cuda_fp16.h>
#include <math.h>
#include <stdint.h>

// ---------------- problem constants ----------------
#define Bsz   32
#define Cch   384
#define Hh    56
#define Wwid  56
#define WS    7
#define SSH   3
#define NHd   12
#define Ntok  49
#define HDim  32
#define HIDd  1536
#define NWTOT 2048
#define Mrows (NWTOT*Ntok)         // 100352
#define SCALE 0.17677669529663687f

// ---------------- scratch: fp32 residual chain + fp16 GEMM operands ----------
constexpr size_t OFF_XRAW = 0;                                  // [M,384] f32
constexpr size_t OFF_Y    = OFF_XRAW + (size_t)Mrows*Cch;       // [M,384] f32
constexpr size_t OFF_FIN  = OFF_Y    + (size_t)Mrows*Cch;       // [M,384] f32
constexpr size_t SCRATCH_F = OFF_FIN + (size_t)Mrows*Cch;

constexpr size_t HOFF_XLN  = 0;                                 // [M,384]
constexpr size_t HOFF_QKV  = HOFF_XLN  + (size_t)Mrows*Cch;     // [M,1152]
constexpr size_t HOFF_ATT  = HOFF_QKV  + (size_t)Mrows*(3*Cch); // [M,384]
constexpr size_t HOFF_YLN  = HOFF_ATT  + (size_t)Mrows*Cch;     // [M,384]
constexpr size_t HOFF_H    = HOFF_YLN  + (size_t)Mrows*Cch;     // [M,1536]
constexpr size_t HOFF_WQKV = HOFF_H    + (size_t)Mrows*HIDd;    // [1152][384]
constexpr size_t HOFF_WPRJ = HOFF_WQKV + (size_t)1152*384;      // [384][384]
constexpr size_t HOFF_WFC1 = HOFF_WPRJ + (size_t)384*384;       // [1536][384]
constexpr size_t HOFF_WFC2 = HOFF_WFC1 + (size_t)1536*384;      // [384][1536]
constexpr size_t SCRATCH_H = HOFF_WFC2 + (size_t)384*1536;

__device__ __align__(16) float  g_f[SCRATCH_F];
__device__ __align__(16) __half g_h[SCRATCH_H];

// ---------------- helpers ----------------
__device__ __forceinline__ int region(int p) {
    return p < (Hh - WS) ? 0 : (p < (Hh - SSH) ? 1 : 2);
}
__device__ __forceinline__ float gelu_exact(float v) {
    return 0.5f * v * (1.0f + erff(v * 0.70710678118654752f));
}
__device__ __forceinline__ void mma_f16(float c[4], const uint32_t a[4], const uint32_t b[2]) {
    asm volatile(
        "mma.sync.aligned.m16n8k16.row.col.f32.f16.f16.f32 "
        "{%0,%1,%2,%3}, {%4,%5,%6,%7}, {%8,%9}, {%0,%1,%2,%3};\n"
        : "+f"(c[0]), "+f"(c[1]), "+f"(c[2]), "+f"(c[3])
        : "r"(a[0]), "r"(a[1]), "r"(a[2]), "r"(a[3]), "r"(b[0]), "r"(b[1]));
}
__device__ __forceinline__ void cpa16(uint32_t dst, const void* src) {
    asm volatile("cp.async.cg.shared.global [%0], [%1], 16;" :: "r"(dst), "l"(src));
}
__device__ __forceinline__ void cpa_commit() {
    asm volatile("cp.async.commit_group;" ::: "memory");
}
template <int N>
__device__ __forceinline__ void cpa_wait() {
    asm volatile("cp.async.wait_group %0;" :: "n"(N) : "memory");
}

// ---------------- transpose-in (fp32, NCHW -> m-order) ----------------
__global__ void __launch_bounds__(256) tin_kernel(const float* __restrict__ x) {
    int ct = blockIdx.x, hh = blockIdx.y, b = blockIdx.z;
    __shared__ float tile[32][57];
    int h0 = hh + SSH; if (h0 >= Hh) h0 -= Hh;
    for (int idx = threadIdx.x; idx < 32*56; idx += 256) {
        int i = idx / 56, ws = idx - i*56;
        tile[i][ws] = x[((size_t)(b*Cch + ct*32 + i))*(Hh*Wwid) + h0*Wwid + ws];
    }
    __syncthreads();
    int wh = hh / WS, r = hh % WS;
    for (int idx = threadIdx.x; idx < 56*32; idx += 256) {
        int t = idx >> 5, i = idx & 31;
        int wsrc = t + SSH; if (wsrc >= Wwid) wsrc -= Wwid;
        int ww = t / WS, c = t % WS;
        int m = (((b*8 + wh)*8 + ww)*Ntok) + r*WS + c;
        g_f[OFF_XRAW + (size_t)m*Cch + ct*32 + i] = tile[i][wsrc];
    }
}

// ---------------- transpose-out ----------------
__global__ void __launch_bounds__(256) tout_kernel(float* __restrict__ out) {
    int ct = blockIdx.x, h0 = blockIdx.y, b = blockIdx.z;
    __shared__ float tile[32][57];
    int hh = h0 - SSH; if (hh < 0) hh += Hh;
    int wh = hh / WS, r = hh % WS;
    for (int idx = threadIdx.x; idx < 56*32; idx += 256) {
        int t = idx >> 5, i = idx & 31;
        int ww = t / WS, c = t % WS;
        int m = (((b*8 + wh)*8 + ww)*Ntok) + r*WS + c;
        int w0 = t + SSH; if (w0 >= Wwid) w0 -= Wwid;
        tile[i][w0] = g_f[OFF_FIN + (size_t)m*Cch + ct*32 + i];
    }
    __syncthreads();
    for (int idx = threadIdx.x; idx < 32*56; idx += 256) {
        int i = idx / 56, w0 = idx - i*56;
        out[((size_t)(b*Cch + ct*32 + i))*(Hh*Wwid) + h0*Wwid + w0] = tile[i][w0];
    }
}

// ---------------- weight transpose [K][N] f32 -> [N][K] half ----------------
__global__ void __launch_bounds__(256) wtrans_kernel(const float* __restrict__ W,
                                                     int K, int N, size_t outoff) {
    __shared__ float t[32][33];
    int n0 = blockIdx.x*32, k0 = blockIdx.y*32;
    int tx = threadIdx.x & 31, ty = threadIdx.x >> 5;
    __half* out = g_h + outoff;
    for (int i = ty; i < 32; i += 8)
        t[i][tx] = W[(size_t)(k0+i)*N + n0+tx];
    __syncthreads();
    for (int i = ty; i < 32; i += 8)
        out[(size_t)(n0+i)*K + k0+tx] = __float2half_rn(t[tx][i]);
}

// ---------------- layernorm: fp32 in -> fp16 out ----------------
__global__ void __launch_bounds__(128) ln_kernel(size_t Xoff, const float* __restrict__ gam,
                                                 const float* __restrict__ bet, size_t Yoff) {
    int row = blockIdx.x;
    const float* x = g_f + Xoff + (size_t)row*Cch;
    __half*      y = g_h + Yoff + (size_t)row*Cch;
    int c = threadIdx.x;
    float v0 = x[c], v1 = x[c+128], v2 = x[c+256];
    float s = v0+v1+v2, s2 = v0*v0 + v1*v1 + v2*v2;
    #pragma unroll
    for (int o = 16; o; o >>= 1) {
        s  += __shfl_xor_sync(0xffffffffu, s,  o);
        s2 += __shfl_xor_sync(0xffffffffu, s2, o);
    }
    __shared__ float rs[4], rs2[4];
    int wid = c >> 5;
    if ((c & 31) == 0) { rs[wid] = s; rs2[wid] = s2; }
    __syncthreads();
    s  = rs[0]+rs[1]+rs[2]+rs[3];
    s2 = rs2[0]+rs2[1]+rs2[2]+rs2[3];
    float mean = s * (1.0f/Cch);
    float var  = s2 * (1.0f/Cch) - mean*mean;
    float inv  = rsqrtf(var + 1e-5f);
    y[c]     = __float2half_rn((v0-mean)*inv*gam[c]     + bet[c]);
    y[c+128] = __float2half_rn((v1-mean)*inv*gam[c+128] + bet[c+128]);
    y[c+256] = __float2half_rn((v2-mean)*inv*gam[c+256] + bet[c+256]);
}

// ---------------- fp16 GEMM: 128x128 block, BK=16, 4-stage cp.async ----------
// A [M][K] half (row-major), B [N][K] half (K-contiguous). Warp tile 64x32.
#define EPI_BIAS_H 0   // + bias -> half C
#define EPI_RES_F  1   // + bias + fp32 residual -> fp32 C
#define EPI_GELU_H 2   // + bias, gelu -> half C

#define HRS 24                  // smem row stride in halves (48B) — conflict-free
#define HA_STG (128*HRS)        // per-stage A halves
#define HB_STG (128*HRS)        // per-stage B halves
#define STAGES 4
constexpr int SMEM_HGEMM_BYTES = STAGES * (HA_STG + HB_STG) * 2;   // 49152

__global__ void __launch_bounds__(256, 2) hgemm_kernel(
    size_t Aoff, size_t Boff, const float* __restrict__ bias,
    long long resoff, size_t Coff, int N, int K, int epi)
{
    extern __shared__ __half smh[];
    __half* As = smh;
    __half* Bs = smh + STAGES*HA_STG;
    uint32_t as_sm = (uint32_t)__cvta_generic_to_shared(As);
    uint32_t bs_sm = (uint32_t)__cvta_generic_to_shared(Bs);

    int tid = threadIdx.x;
    int warp = tid >> 5, lane = tid & 31;
    int wrow = warp >> 2, wcol = warp & 3;
    int g = lane >> 2, qc = lane & 3;
    int brow = blockIdx.y, bcol = blockIdx.x;

    const __half* Ablk = g_h + Aoff + (size_t)brow*128*K;
    const __half* Bblk = g_h + Boff + (size_t)bcol*128*K;

    int lrow = tid >> 1;            // 0..127 (same for A and B tiles)
    int lch  = (tid & 1) * 8;       // 0 / 8 halves

    auto load_tile = [&](int s, int kt) {
        const __half* Ap = Ablk + (size_t)lrow*K + kt*16 + lch;
        const __half* Bp = Bblk + (size_t)lrow*K + kt*16 + lch;
        uint32_t off = (uint32_t)(s*HA_STG + lrow*HRS + lch) * 2;
        cpa16(as_sm + off, Ap);
        cpa16(bs_sm + off, Bp);
    };

    float acc[4][4][4];
    #pragma unroll
    for (int i = 0; i < 4; i++)
        #pragma unroll
        for (int j = 0; j < 4; j++)
            #pragma unroll
            for (int r = 0; r < 4; r++) acc[i][j][r] = 0.f;

    int nk = K >> 4;
    load_tile(0, 0); cpa_commit();
    load_tile(1, 1); cpa_commit();
    load_tile(2, 2); cpa_commit();
    cpa_wait<2>();
    __syncthreads();

    int stage = 0;
    for (int kt = 0; kt < nk; kt++) {
        if (kt + 3 < nk) {
            int s = stage + 3 >= STAGES ? stage + 3 - STAGES : stage + 3;
            load_tile(s, kt + 3);
        }
        cpa_commit();

        const __half* Asb = As + stage*HA_STG;
        const __half* Bsb = Bs + stage*HB_STG;
        uint32_t af[4][4];
        #pragma unroll
        for (int i = 0; i < 4; i++) {
            int r = wrow*64 + i*16 + g;
            af[i][0] = *(const uint32_t*)(Asb + r*HRS     + 2*qc);
            af[i][1] = *(const uint32_t*)(Asb + (r+8)*HRS + 2*qc);
            af[i][2] = *(const uint32_t*)(Asb + r*HRS     + 2*qc + 8);
            af[i][3] = *(const uint32_t*)(Asb + (r+8)*HRS + 2*qc + 8);
        }
        uint32_t bf[4][2];
        #pragma unroll
        for (int j = 0; j < 4; j++) {
            int c = wcol*32 + j*8 + g;
            bf[j][0] = *(const uint32_t*)(Bsb + c*HRS + 2*qc);
            bf[j][1] = *(const uint32_t*)(Bsb + c*HRS + 2*qc + 8);
        }
        #pragma unroll
        for (int i = 0; i < 4; i++)
            #pragma unroll
            for (int j = 0; j < 4; j++)
                mma_f16(acc[i][j], af[i], bf[j]);

        cpa_wait<2>();
        __syncthreads();
        stage = stage + 1 == STAGES ? 0 : stage + 1;
    }

    const float* res = (resoff >= 0) ? (g_f + (size_t)resoff) : nullptr;
    #pragma unroll
    for (int i = 0; i < 4; i++) {
        int r0 = brow*128 + wrow*64 + i*16 + g;
        #pragma unroll
        for (int j = 0; j < 4; j++) {
            int cb = bcol*128 + wcol*32 + j*8 + qc*2;
            float bx = bias[cb], by = bias[cb+1];
            #pragma unroll
            for (int half_ = 0; half_ < 2; half_++) {
                int row = r0 + half_*8;
                float vx = acc[i][j][half_*2]   + bx;
                float vy = acc[i][j][half_*2+1] + by;
                if (epi == EPI_RES_F) {
                    float2 rr = *(const float2*)(res + (size_t)row*N + cb);
                    vx += rr.x; vy += rr.y;
                    float2 o = {vx, vy};
                    *(float2*)(g_f + Coff + (size_t)row*N + cb) = o;
                } else {
                    if (epi == EPI_GELU_H) { vx = gelu_exact(vx); vy = gelu_exact(vy); }
                    *(__half2*)(g_h + Coff + (size_t)row*N + cb) =
                        __floats2half2_rn(vx, vy);
                }
            }
        }
    }
}

// ---------------- windowed attention: half QKV in, half ATT out --------------
__global__ void __launch_bounds__(128) attn_kernel(const float* __restrict__ rpb) {
    int blk = blockIdx.x;
    int h = blk % NHd;
    int w = blk / NHd;
    int ww = w & 7, wh = (w >> 3) & 7;
    int m0 = w * Ntok;
    __shared__ float q[Ntok][36], kk[Ntok][36], vv[Ntok][36];
    __shared__ float sc[Ntok][52];
    __shared__ int   rid[Ntok];
    int tid = threadIdx.x;

    const __half* qkv = g_h + HOFF_QKV;
    for (int idx = tid; idx < Ntok*8; idx += 128) {
        int i = idx >> 3, dq = (idx & 7) * 4;
        size_t base = (size_t)(m0 + i)*(3*Cch) + h*HDim + dq;
        const __half2* qp = (const __half2*)(qkv + base);
        const __half2* kp = (const __half2*)(qkv + base + Cch);
        const __half2* vp = (const __half2*)(qkv + base + 2*Cch);
        float2 q0 = __half22float2(qp[0]), q1 = __half22float2(qp[1]);
        float2 k0 = __half22float2(kp[0]), k1 = __half22float2(kp[1]);
        float2 v0 = __half22float2(vp[0]), v1 = __half22float2(vp[1]);
        q[i][dq]   = q0.x*SCALE; q[i][dq+1] = q0.y*SCALE;
        q[i][dq+2] = q1.x*SCALE; q[i][dq+3] = q1.y*SCALE;
        kk[i][dq]   = k0.x; kk[i][dq+1] = k0.y;
        kk[i][dq+2] = k1.x; kk[i][dq+3] = k1.y;
        vv[i][dq]   = v0.x; vv[i][dq+1] = v0.y;
        vv[i][dq+2] = v1.x; vv[i][dq+3] = v1.y;
    }
    if (tid < Ntok) {
        int r = tid / WS, c = tid % WS;
        rid[tid] = region(wh*WS + r)*3 + region(ww*WS + c);
    }
    __syncthreads();

    // QK^T: 4x4 blocks with interleaved rows {b, b+13, b+26, b+39}
    for (int t = tid; t < 169; t += 128) {
        int ib = t / 13, jb = t % 13;
        int ir[4] = { ib, ib+13, ib+26, (ib+39 < Ntok) ? ib+39 : 48 };
        int jr[4] = { jb, jb+13, jb+26, (jb+39 < Ntok) ? jb+39 : 48 };
        float a[4][4];
        #pragma unroll
        for (int r = 0; r < 4; r++)
            #pragma unroll
            for (int s = 0; s < 4; s++) a[r][s] = 0.f;
        #pragma unroll
        for (int d = 0; d < HDim; d += 4) {
            float4 qv[4], kv[4];
            #pragma unroll
            for (int r = 0; r < 4; r++) qv[r] = *(const float4*)(&q[ir[r]][d]);
            #pragma unroll
            for (int s = 0; s < 4; s++) kv[s] = *(const float4*)(&kk[jr[s]][d]);
            #pragma unroll
            for (int r = 0; r < 4; r++)
                #pragma unroll
                for (int s = 0; s < 4; s++)
                    a[r][s] = fmaf(qv[r].x, kv[s].x, fmaf(qv[r].y, kv[s].y,
                              fmaf(qv[r].z, kv[s].z, fmaf(qv[r].w, kv[s].w, a[r][s]))));
        }
        #pragma unroll
        for (int r = 0; r < 4; r++) {
            if (r == 3 && ib + 39 >= Ntok) continue;
            int i = ir[r];
            int ri = i / WS, ci = i % WS, rdi = rid[i];
            #pragma unroll
            for (int s = 0; s < 4; s++) {
                if (s == 3 && jb + 39 >= Ntok) continue;
                int j = jr[s];
                int rj = j / WS, cj = j % WS;
                int rpi = (ri - rj + WS - 1)*(2*WS - 1) + (ci - cj + WS - 1);
                float v = a[r][s] + rpb[rpi*NHd + h];
                if (rdi != rid[j]) v -= 100.0f;
                sc[i][j] = v;
            }
        }
    }
    __syncthreads();

    // softmax: 2 threads per row
    {
        int i = tid >> 1, p = tid & 1;
        bool act = i < Ntok;
        int ic = act ? i : 48;
        float mx = -1e30f;
        for (int j = p; j < Ntok; j += 2) mx = fmaxf(mx, sc[ic][j]);
        mx = fmaxf(mx, __shfl_xor_sync(0xffffffffu, mx, 1));
        float sum = 0.f;
        for (int j = p; j < Ntok; j += 2) {
            float e = __expf(sc[ic][j] - mx);
            if (act) sc[ic][j] = e;
            sum += e;
        }
        sum += __shfl_xor_sync(0xffffffffu, sum, 1);
        float inv = 1.0f / sum;
        if (act)
            for (int j = p; j < Ntok; j += 2) sc[ic][j] *= inv;
    }
    __syncthreads();

    // AV -> half ATT
    __half* att = g_h + HOFF_ATT;
    if (tid < 100) {
        int ip = tid >> 2, cb = (tid & 3) * 8;
        int i0 = 2*ip, i1p = 2*ip + 1;
        int i1 = (i1p < Ntok) ? i1p : 48;
        float a0[8], a1[8];
        #pragma unroll
        for (int c = 0; c < 8; c++) { a0[c] = 0.f; a1[c] = 0.f; }
        for (int j = 0; j < Ntok; j++) {
            float s0 = sc[i0][j], s1 = sc[i1][j];
            float4 va = *(const float4*)(&vv[j][cb]);
            float4 vb = *(const float4*)(&vv[j][cb+4]);
            a0[0]=fmaf(s0,va.x,a0[0]); a0[1]=fmaf(s0,va.y,a0[1]);
            a0[2]=fmaf(s0,va.z,a0[2]); a0[3]=fmaf(s0,va.w,a0[3]);
            a0[4]=fmaf(s0,vb.x,a0[4]); a0[5]=fmaf(s0,vb.y,a0[5]);
            a0[6]=fmaf(s0,vb.z,a0[6]); a0[7]=fmaf(s0,vb.w,a0[7]);
            a1[0]=fmaf(s1,va.x,a1[0]); a1[1]=fmaf(s1,va.y,a1[1]);
            a1[2]=fmaf(s1,va.z,a1[2]); a1[3]=fmaf(s1,va.w,a1[3]);
            a1[4]=fmaf(s1,vb.x,a1[4]); a1[5]=fmaf(s1,vb.y,a1[5]);
            a1[6]=fmaf(s1,vb.z,a1[6]); a1[7]=fmaf(s1,vb.w,a1[7]);
        }
        __half2 p0[4] = { __floats2half2_rn(a0[0],a0[1]), __floats2half2_rn(a0[2],a0[3]),
                          __floats2half2_rn(a0[4],a0[5]), __floats2half2_rn(a0[6],a0[7]) };
        *(uint4*)(att + (size_t)(m0 + i0)*Cch + h*HDim + cb) = *(const uint4*)p0;
        if (i1p < Ntok) {
            __half2 p1[4] = { __floats2half2_rn(a1[0],a1[1]), __floats2half2_rn(a1[2],a1[3]),
                              __floats2half2_rn(a1[4],a1[5]), __floats2half2_rn(a1[6],a1[7]) };
            *(uint4*)(att + (size_t)(m0 + i1p)*Cch + h*HDim + cb) = *(const uint4*)p1;
        }
    }
}

// ---------------- launch ----------------
extern "C" void kernel_launch(void* const* d_in, const int* in_sizes, int n_in,
                              void* d_out, int out_size) {
    const float* x      = (const float*)d_in[0];
    const float* qkv_w  = (const float*)d_in[1];
    const float* qkv_b  = (const float*)d_in[2];
    const float* proj_w = (const float*)d_in[3];
    const float* proj_b = (const float*)d_in[4];
    const float* rpb    = (const float*)d_in[5];
    const float* n1w    = (const float*)d_in[6];
    const float* n1b    = (const float*)d_in[7];
    const float* n2w    = (const float*)d_in[8];
    const float* n2b    = (const float*)d_in[9];
    const float* fc1w   = (const float*)d_in[10];
    const float* fc1b   = (const float*)d_in[11];
    const float* fc2w   = (const float*)d_in[12];
    const float* fc2b   = (const float*)d_in[13];
    float* out = (float*)d_out;

    cudaFuncSetAttribute(hgemm_kernel, cudaFuncAttributeMaxDynamicSharedMemorySize,
                         SMEM_HGEMM_BYTES);

    // weight prep: [K][N] f32 -> [N][K] half
    wtrans_kernel<<<dim3(1152/32, 384/32), 256>>>(qkv_w, Cch, 1152, HOFF_WQKV);
    wtrans_kernel<<<dim3(384/32,  384/32), 256>>>(proj_w, Cch, 384,  HOFF_WPRJ);
    wtrans_kernel<<<dim3(1536/32, 384/32), 256>>>(fc1w,  Cch, 1536, HOFF_WFC1);
    wtrans_kernel<<<dim3(384/32, 1536/32), 256>>>(fc2w,  HIDd, 384, HOFF_WFC2);

    tin_kernel<<<dim3(12, 56, 32), 256>>>(x);
    ln_kernel<<<Mrows, 128>>>(OFF_XRAW, n1w, n1b, HOFF_XLN);
    hgemm_kernel<<<dim3(1152/128, Mrows/128), 256, SMEM_HGEMM_BYTES>>>(
        HOFF_XLN, HOFF_WQKV, qkv_b, -1, HOFF_QKV, 1152, Cch, EPI_BIAS_H);
    attn_kernel<<<NWTOT * NHd, 128>>>(rpb);
    hgemm_kernel<<<dim3(384/128, Mrows/128), 256, SMEM_HGEMM_BYTES>>>(
        HOFF_ATT, HOFF_WPRJ, proj_b, (long long)OFF_XRAW, OFF_Y, Cch, Cch, EPI_RES_F);
    ln_kernel<<<Mrows, 128>>>(OFF_Y, n2w, n2b, HOFF_YLN);
    hgemm_kernel<<<dim3(1536/128, Mrows/128), 256, SMEM_HGEMM_BYTES>>>(
        HOFF_YLN, HOFF_WFC1, fc1b, -1, HOFF_H, HIDd, Cch, EPI_GELU_H);
    hgemm_kernel<<<dim3(384/128, Mrows/128), 256, SMEM_HGEMM_BYTES>>>(
        HOFF_H, HOFF_WFC2, fc2b, (long long)OFF_Y, OFF_FIN, Cch, HIDd, EPI_RES_F);
    tout_kernel<<<dim3(12, 56, 32), 256>>>(out);
}

// round 9
// speedup vs baseline: 4.0656x; 1.0646x over previous
#include <cuda_runtime.h>
#include <cuda_fp16.h>
#include <math.h>
#include <stdint.h>

// ---------------- problem constants ----------------
#define Bsz   32
#define Cch   384
#define Hh    56
#define Wwid  56
#define WS    7
#define SSH   3
#define NHd   12
#define Ntok  49
#define HDim  32
#define HIDd  1536
#define NWTOT 2048
#define Mrows (NWTOT*Ntok)         // 100352
#define SCALE 0.17677669529663687f

// ---------------- scratch: fp32 residual chain + fp16 GEMM operands ----------
constexpr size_t OFF_XRAW = 0;                                  // [M,384] f32
constexpr size_t OFF_Y    = OFF_XRAW + (size_t)Mrows*Cch;       // [M,384] f32
constexpr size_t OFF_FIN  = OFF_Y    + (size_t)Mrows*Cch;       // [M,384] f32
constexpr size_t SCRATCH_F = OFF_FIN + (size_t)Mrows*Cch;

constexpr size_t HOFF_XLN  = 0;                                 // [M,384]
constexpr size_t HOFF_QKV  = HOFF_XLN  + (size_t)Mrows*Cch;     // [M,1152]
constexpr size_t HOFF_ATT  = HOFF_QKV  + (size_t)Mrows*(3*Cch); // [M,384]
constexpr size_t HOFF_YLN  = HOFF_ATT  + (size_t)Mrows*Cch;     // [M,384]
constexpr size_t HOFF_H    = HOFF_YLN  + (size_t)Mrows*Cch;     // [M,1536]
constexpr size_t HOFF_WQKV = HOFF_H    + (size_t)Mrows*HIDd;    // [1152][384]
constexpr size_t HOFF_WPRJ = HOFF_WQKV + (size_t)1152*384;      // [384][384]
constexpr size_t HOFF_WFC1 = HOFF_WPRJ + (size_t)384*384;       // [1536][384]
constexpr size_t HOFF_WFC2 = HOFF_WFC1 + (size_t)1536*384;      // [384][1536]
constexpr size_t SCRATCH_H = HOFF_WFC2 + (size_t)384*1536;

__device__ __align__(16) float  g_f[SCRATCH_F];
__device__ __align__(16) __half g_h[SCRATCH_H];

// ---------------- helpers ----------------
__device__ __forceinline__ int region(int p) {
    return p < (Hh - WS) ? 0 : (p < (Hh - SSH) ? 1 : 2);
}
__device__ __forceinline__ float gelu_exact(float v) {
    return 0.5f * v * (1.0f + erff(v * 0.70710678118654752f));
}
__device__ __forceinline__ void mma_f16(float c[4], const uint32_t a[4], const uint32_t b[2]) {
    asm volatile(
        "mma.sync.aligned.m16n8k16.row.col.f32.f16.f16.f32 "
        "{%0,%1,%2,%3}, {%4,%5,%6,%7}, {%8,%9}, {%0,%1,%2,%3};\n"
        : "+f"(c[0]), "+f"(c[1]), "+f"(c[2]), "+f"(c[3])
        : "r"(a[0]), "r"(a[1]), "r"(a[2]), "r"(a[3]), "r"(b[0]), "r"(b[1]));
}
__device__ __forceinline__ void cpa16(uint32_t dst, const void* src) {
    asm volatile("cp.async.cg.shared.global [%0], [%1], 16;" :: "r"(dst), "l"(src));
}
__device__ __forceinline__ void cpa_commit() {
    asm volatile("cp.async.commit_group;" ::: "memory");
}
template <int N>
__device__ __forceinline__ void cpa_wait() {
    asm volatile("cp.async.wait_group %0;" :: "n"(N) : "memory");
}

// ---------------- transpose-in (fp32, NCHW -> m-order) ----------------
__global__ void __launch_bounds__(256) tin_kernel(const float* __restrict__ x) {
    int ct = blockIdx.x, hh = blockIdx.y, b = blockIdx.z;
    __shared__ float tile[32][57];
    int h0 = hh + SSH; if (h0 >= Hh) h0 -= Hh;
    for (int idx = threadIdx.x; idx < 32*56; idx += 256) {
        int i = idx / 56, ws = idx - i*56;
        tile[i][ws] = x[((size_t)(b*Cch + ct*32 + i))*(Hh*Wwid) + h0*Wwid + ws];
    }
    __syncthreads();
    int wh = hh / WS, r = hh % WS;
    for (int idx = threadIdx.x; idx < 56*32; idx += 256) {
        int t = idx >> 5, i = idx & 31;
        int wsrc = t + SSH; if (wsrc >= Wwid) wsrc -= Wwid;
        int ww = t / WS, c = t % WS;
        int m = (((b*8 + wh)*8 + ww)*Ntok) + r*WS + c;
        g_f[OFF_XRAW + (size_t)m*Cch + ct*32 + i] = tile[i][wsrc];
    }
}

// ---------------- transpose-out ----------------
__global__ void __launch_bounds__(256) tout_kernel(float* __restrict__ out) {
    int ct = blockIdx.x, h0 = blockIdx.y, b = blockIdx.z;
    __shared__ float tile[32][57];
    int hh = h0 - SSH; if (hh < 0) hh += Hh;
    int wh = hh / WS, r = hh % WS;
    for (int idx = threadIdx.x; idx < 56*32; idx += 256) {
        int t = idx >> 5, i = idx & 31;
        int ww = t / WS, c = t % WS;
        int m = (((b*8 + wh)*8 + ww)*Ntok) + r*WS + c;
        int w0 = t + SSH; if (w0 >= Wwid) w0 -= Wwid;
        tile[i][w0] = g_f[OFF_FIN + (size_t)m*Cch + ct*32 + i];
    }
    __syncthreads();
    for (int idx = threadIdx.x; idx < 32*56; idx += 256) {
        int i = idx / 56, w0 = idx - i*56;
        out[((size_t)(b*Cch + ct*32 + i))*(Hh*Wwid) + h0*Wwid + w0] = tile[i][w0];
    }
}

// ---------------- weight transpose [K][N] f32 -> [N][K] half ----------------
__global__ void __launch_bounds__(256) wtrans_kernel(const float* __restrict__ W,
                                                     int K, int N, size_t outoff) {
    __shared__ float t[32][33];
    int n0 = blockIdx.x*32, k0 = blockIdx.y*32;
    int tx = threadIdx.x & 31, ty = threadIdx.x >> 5;
    __half* out = g_h + outoff;
    for (int i = ty; i < 32; i += 8)
        t[i][tx] = W[(size_t)(k0+i)*N + n0+tx];
    __syncthreads();
    for (int i = ty; i < 32; i += 8)
        out[(size_t)(n0+i)*K + k0+tx] = __float2half_rn(t[tx][i]);
}

// ---------------- layernorm: fp32 in -> fp16 out ----------------
__global__ void __launch_bounds__(128) ln_kernel(size_t Xoff, const float* __restrict__ gam,
                                                 const float* __restrict__ bet, size_t Yoff) {
    int row = blockIdx.x;
    const float* x = g_f + Xoff + (size_t)row*Cch;
    __half*      y = g_h + Yoff + (size_t)row*Cch;
    int c = threadIdx.x;
    float v0 = x[c], v1 = x[c+128], v2 = x[c+256];
    float s = v0+v1+v2, s2 = v0*v0 + v1*v1 + v2*v2;
    #pragma unroll
    for (int o = 16; o; o >>= 1) {
        s  += __shfl_xor_sync(0xffffffffu, s,  o);
        s2 += __shfl_xor_sync(0xffffffffu, s2, o);
    }
    __shared__ float rs[4], rs2[4];
    int wid = c >> 5;
    if ((c & 31) == 0) { rs[wid] = s; rs2[wid] = s2; }
    __syncthreads();
    s  = rs[0]+rs[1]+rs[2]+rs[3];
    s2 = rs2[0]+rs2[1]+rs2[2]+rs2[3];
    float mean = s * (1.0f/Cch);
    float var  = s2 * (1.0f/Cch) - mean*mean;
    float inv  = rsqrtf(var + 1e-5f);
    y[c]     = __float2half_rn((v0-mean)*inv*gam[c]     + bet[c]);
    y[c+128] = __float2half_rn((v1-mean)*inv*gam[c+128] + bet[c+128]);
    y[c+256] = __float2half_rn((v2-mean)*inv*gam[c+256] + bet[c+256]);
}

// ---------------- fp16 GEMM: 128x128 block, BK=16, 4-stage cp.async ----------
#define EPI_BIAS_H 0
#define EPI_RES_F  1
#define EPI_GELU_H 2

#define HRS 24
#define HA_STG (128*HRS)
#define HB_STG (128*HRS)
#define STAGES 4
constexpr int SMEM_HGEMM_BYTES = STAGES * (HA_STG + HB_STG) * 2;   // 49152

__global__ void __launch_bounds__(256, 2) hgemm_kernel(
    size_t Aoff, size_t Boff, const float* __restrict__ bias,
    long long resoff, size_t Coff, int N, int K, int epi)
{
    extern __shared__ __half smh[];
    __half* As = smh;
    __half* Bs = smh + STAGES*HA_STG;
    uint32_t as_sm = (uint32_t)__cvta_generic_to_shared(As);
    uint32_t bs_sm = (uint32_t)__cvta_generic_to_shared(Bs);

    int tid = threadIdx.x;
    int warp = tid >> 5, lane = tid & 31;
    int wrow = warp >> 2, wcol = warp & 3;
    int g = lane >> 2, qc = lane & 3;
    int brow = blockIdx.y, bcol = blockIdx.x;

    const __half* Ablk = g_h + Aoff + (size_t)brow*128*K;
    const __half* Bblk = g_h + Boff + (size_t)bcol*128*K;

    int lrow = tid >> 1;
    int lch  = (tid & 1) * 8;

    auto load_tile = [&](int s, int kt) {
        const __half* Ap = Ablk + (size_t)lrow*K + kt*16 + lch;
        const __half* Bp = Bblk + (size_t)lrow*K + kt*16 + lch;
        uint32_t off = (uint32_t)(s*HA_STG + lrow*HRS + lch) * 2;
        cpa16(as_sm + off, Ap);
        cpa16(bs_sm + off, Bp);
    };

    float acc[4][4][4];
    #pragma unroll
    for (int i = 0; i < 4; i++)
        #pragma unroll
        for (int j = 0; j < 4; j++)
            #pragma unroll
            for (int r = 0; r < 4; r++) acc[i][j][r] = 0.f;

    int nk = K >> 4;
    load_tile(0, 0); cpa_commit();
    load_tile(1, 1); cpa_commit();
    load_tile(2, 2); cpa_commit();
    cpa_wait<2>();
    __syncthreads();

    int stage = 0;
    for (int kt = 0; kt < nk; kt++) {
        if (kt + 3 < nk) {
            int s = stage + 3 >= STAGES ? stage + 3 - STAGES : stage + 3;
            load_tile(s, kt + 3);
        }
        cpa_commit();

        const __half* Asb = As + stage*HA_STG;
        const __half* Bsb = Bs + stage*HB_STG;
        uint32_t af[4][4];
        #pragma unroll
        for (int i = 0; i < 4; i++) {
            int r = wrow*64 + i*16 + g;
            af[i][0] = *(const uint32_t*)(Asb + r*HRS     + 2*qc);
            af[i][1] = *(const uint32_t*)(Asb + (r+8)*HRS + 2*qc);
            af[i][2] = *(const uint32_t*)(Asb + r*HRS     + 2*qc + 8);
            af[i][3] = *(const uint32_t*)(Asb + (r+8)*HRS + 2*qc + 8);
        }
        uint32_t bf[4][2];
        #pragma unroll
        for (int j = 0; j < 4; j++) {
            int c = wcol*32 + j*8 + g;
            bf[j][0] = *(const uint32_t*)(Bsb + c*HRS + 2*qc);
            bf[j][1] = *(const uint32_t*)(Bsb + c*HRS + 2*qc + 8);
        }
        #pragma unroll
        for (int i = 0; i < 4; i++)
            #pragma unroll
            for (int j = 0; j < 4; j++)
                mma_f16(acc[i][j], af[i], bf[j]);

        cpa_wait<2>();
        __syncthreads();
        stage = stage + 1 == STAGES ? 0 : stage + 1;
    }

    const float* res = (resoff >= 0) ? (g_f + (size_t)resoff) : nullptr;
    #pragma unroll
    for (int i = 0; i < 4; i++) {
        int r0 = brow*128 + wrow*64 + i*16 + g;
        #pragma unroll
        for (int j = 0; j < 4; j++) {
            int cb = bcol*128 + wcol*32 + j*8 + qc*2;
            float bx = bias[cb], by = bias[cb+1];
            #pragma unroll
            for (int half_ = 0; half_ < 2; half_++) {
                int row = r0 + half_*8;
                float vx = acc[i][j][half_*2]   + bx;
                float vy = acc[i][j][half_*2+1] + by;
                if (epi == EPI_RES_F) {
                    float2 rr = *(const float2*)(res + (size_t)row*N + cb);
                    vx += rr.x; vy += rr.y;
                    float2 o = {vx, vy};
                    *(float2*)(g_f + Coff + (size_t)row*N + cb) = o;
                } else {
                    if (epi == EPI_GELU_H) { vx = gelu_exact(vx); vy = gelu_exact(vy); }
                    *(__half2*)(g_h + Coff + (size_t)row*N + cb) =
                        __floats2half2_rn(vx, vy);
                }
            }
        }
    }
}

// ---------------- tensor-core windowed attention -----------------------------
// One block per (window, head), 128 threads / 4 warps.
// QK^T: A=Q[token][dim] row-major, B=K[token][dim] (col-major KxN, k=dim).
// P.V : A=Ph[query][token] row-major, B=vT[dim][token] (col-major, k=token).
__global__ void __launch_bounds__(128) attn_kernel(const float* __restrict__ rpb) {
    int blk = blockIdx.x;
    int h = blk % NHd;
    int w = blk / NHd;
    int ww = w & 7, wh = (w >> 3) & 7;
    int m0 = w * Ntok;

    __shared__ __half qh[64][40];    // stride 40h: conflict-free A frags
    __shared__ __half kh[56][40];
    __shared__ __half vT[32][72];    // [dim][token], stride 72h
    __shared__ float  P[49][60];
    __shared__ __half Ph[64][72];
    __shared__ int    rid[Ntok];

    int tid = threadIdx.x;
    int warp = tid >> 5, lane = tid & 31;
    int g = lane >> 2, qc = lane & 3;

    // zero vT and Ph (pad tokens/rows MUST be 0 for the padded AV k-range)
    {
        uint32_t* z1 = (uint32_t*)&vT[0][0];
        #pragma unroll 4
        for (int i = tid; i < 32*72/2; i += 128) z1[i] = 0;
        uint32_t* z2 = (uint32_t*)&Ph[0][0];
        #pragma unroll 4
        for (int i = tid; i < 64*72/2; i += 128) z2[i] = 0;
    }
    __syncthreads();

    const __half* qkv = g_h + HOFF_QKV;
    if (tid < 98) {
        int i = tid >> 1, p = tid & 1;   // token, 16-dim half
        const __half* base = qkv + (size_t)(m0 + i)*(3*Cch) + h*HDim + p*16;
        *(uint4*)&qh[i][p*16]     = *(const uint4*)(base);
        *(uint4*)&qh[i][p*16 + 8] = *(const uint4*)(base + 8);
        *(uint4*)&kh[i][p*16]     = *(const uint4*)(base + Cch);
        *(uint4*)&kh[i][p*16 + 8] = *(const uint4*)(base + Cch + 8);
        const __half* vbase = base + 2*Cch;
        #pragma unroll
        for (int d = 0; d < 16; d++)
            vT[p*16 + d][i] = vbase[d];
    }
    if (tid < Ntok) {
        int r = tid / WS, c = tid % WS;
        rid[tid] = region(wh*WS + r)*3 + region(ww*WS + c);
    }
    __syncthreads();

    // ---- QK^T (warp = 16-row band; 7 col tiles; k = 2 steps of 16 dims) ----
    {
        int r = warp*16 + g;
        uint32_t af[2][4];
        #pragma unroll
        for (int kc = 0; kc < 2; kc++) {
            af[kc][0] = *(const uint32_t*)&qh[r][kc*16 + 2*qc];
            af[kc][1] = *(const uint32_t*)&qh[r+8][kc*16 + 2*qc];
            af[kc][2] = *(const uint32_t*)&qh[r][kc*16 + 2*qc + 8];
            af[kc][3] = *(const uint32_t*)&qh[r+8][kc*16 + 2*qc + 8];
        }
        #pragma unroll
        for (int jt = 0; jt < 7; jt++) {
            float c4[4] = {0.f, 0.f, 0.f, 0.f};
            int col = jt*8 + g;
            uint32_t bf0[2], bf1[2];
            bf0[0] = *(const uint32_t*)&kh[col][2*qc];
            bf0[1] = *(const uint32_t*)&kh[col][2*qc + 8];
            bf1[0] = *(const uint32_t*)&kh[col][16 + 2*qc];
            bf1[1] = *(const uint32_t*)&kh[col][16 + 2*qc + 8];
            mma_f16(c4, af[0], bf0);
            mma_f16(c4, af[1], bf1);
            int c0 = jt*8 + 2*qc;
            #pragma unroll
            for (int u = 0; u < 4; u++) {
                int row = r + (u >> 1)*8;
                int ccol = c0 + (u & 1);
                if (row < Ntok && ccol < Ntok) {
                    int ri = row/WS, ci = row%WS, rj = ccol/WS, cj = ccol%WS;
                    int rpi = (ri - rj + 6)*13 + (ci - cj + 6);
                    float s = c4[u]*SCALE + rpb[rpi*NHd + h];
                    if (rid[row] != rid[ccol]) s -= 100.f;
                    P[row][ccol] = s;
                }
            }
        }
    }
    __syncthreads();

    // ---- softmax (2 threads per row) -> Ph fp16 ----
    {
        int i = tid >> 1, p = tid & 1;
        bool act = (tid < 98);
        int ic = act ? i : 0;
        float mx = -1e30f;
        for (int j = p; j < Ntok; j += 2) mx = fmaxf(mx, P[ic][j]);
        mx = fmaxf(mx, __shfl_xor_sync(0xffffffffu, mx, 1));
        float sum = 0.f;
        for (int j = p; j < Ntok; j += 2) sum += __expf(P[ic][j] - mx);
        sum += __shfl_xor_sync(0xffffffffu, sum, 1);
        float inv = 1.0f / sum;
        if (act)
            for (int j = p; j < Ntok; j += 2)
                Ph[ic][j] = __float2half_rn(__expf(P[ic][j] - mx) * inv);
    }
    __syncthreads();

    // ---- P.V (warp = 16-row band; 4 dim tiles; k = 4 steps of 16 tokens) ----
    {
        int r = warp*16 + g;
        uint32_t af[4][4];
        #pragma unroll
        for (int kc = 0; kc < 4; kc++) {
            af[kc][0] = *(const uint32_t*)&Ph[r][kc*16 + 2*qc];
            af[kc][1] = *(const uint32_t*)&Ph[r+8][kc*16 + 2*qc];
            af[kc][2] = *(const uint32_t*)&Ph[r][kc*16 + 2*qc + 8];
            af[kc][3] = *(const uint32_t*)&Ph[r+8][kc*16 + 2*qc + 8];
        }
        __half* att = g_h + HOFF_ATT;
        #pragma unroll
        for (int ct = 0; ct < 4; ct++) {
            float c4[4] = {0.f, 0.f, 0.f, 0.f};
            int dcol = ct*8 + g;
            #pragma unroll
            for (int kc = 0; kc < 4; kc++) {
                uint32_t bf[2];
                bf[0] = *(const uint32_t*)&vT[dcol][kc*16 + 2*qc];
                bf[1] = *(const uint32_t*)&vT[dcol][kc*16 + 2*qc + 8];
                mma_f16(c4, af[kc], bf);
            }
            int c0 = ct*8 + 2*qc;
            if (r < Ntok)
                *(__half2*)(att + (size_t)(m0 + r)*Cch + h*HDim + c0) =
                    __floats2half2_rn(c4[0], c4[1]);
            if (r + 8 < Ntok)
                *(__half2*)(att + (size_t)(m0 + r + 8)*Cch + h*HDim + c0) =
                    __floats2half2_rn(c4[2], c4[3]);
        }
    }
}

// ---------------- launch ----------------
extern "C" void kernel_launch(void* const* d_in, const int* in_sizes, int n_in,
                              void* d_out, int out_size) {
    const float* x      = (const float*)d_in[0];
    const float* qkv_w  = (const float*)d_in[1];
    const float* qkv_b  = (const float*)d_in[2];
    const float* proj_w = (const float*)d_in[3];
    const float* proj_b = (const float*)d_in[4];
    const float* rpb    = (const float*)d_in[5];
    const float* n1w    = (const float*)d_in[6];
    const float* n1b    = (const float*)d_in[7];
    const float* n2w    = (const float*)d_in[8];
    const float* n2b    = (const float*)d_in[9];
    const float* fc1w   = (const float*)d_in[10];
    const float* fc1b   = (const float*)d_in[11];
    const float* fc2w   = (const float*)d_in[12];
    const float* fc2b   = (const float*)d_in[13];
    float* out = (float*)d_out;

    cudaFuncSetAttribute(hgemm_kernel, cudaFuncAttributeMaxDynamicSharedMemorySize,
                         SMEM_HGEMM_BYTES);

    wtrans_kernel<<<dim3(1152/32, 384/32), 256>>>(qkv_w, Cch, 1152, HOFF_WQKV);
    wtrans_kernel<<<dim3(384/32,  384/32), 256>>>(proj_w, Cch, 384,  HOFF_WPRJ);
    wtrans_kernel<<<dim3(1536/32, 384/32), 256>>>(fc1w,  Cch, 1536, HOFF_WFC1);
    wtrans_kernel<<<dim3(384/32, 1536/32), 256>>>(fc2w,  HIDd, 384, HOFF_WFC2);

    tin_kernel<<<dim3(12, 56, 32), 256>>>(x);
    ln_kernel<<<Mrows, 128>>>(OFF_XRAW, n1w, n1b, HOFF_XLN);
    hgemm_kernel<<<dim3(1152/128, Mrows/128), 256, SMEM_HGEMM_BYTES>>>(
        HOFF_XLN, HOFF_WQKV, qkv_b, -1, HOFF_QKV, 1152, Cch, EPI_BIAS_H);
    attn_kernel<<<NWTOT * NHd, 128>>>(rpb);
    hgemm_kernel<<<dim3(384/128, Mrows/128), 256, SMEM_HGEMM_BYTES>>>(
        HOFF_ATT, HOFF_WPRJ, proj_b, (long long)OFF_XRAW, OFF_Y, Cch, Cch, EPI_RES_F);
    ln_kernel<<<Mrows, 128>>>(OFF_Y, n2w, n2b, HOFF_YLN);
    hgemm_kernel<<<dim3(1536/128, Mrows/128), 256, SMEM_HGEMM_BYTES>>>(
        HOFF_YLN, HOFF_WFC1, fc1b, -1, HOFF_H, HIDd, Cch, EPI_GELU_H);
    hgemm_kernel<<<dim3(384/128, Mrows/128), 256, SMEM_HGEMM_BYTES>>>(
        HOFF_H, HOFF_WFC2, fc2b, (long long)OFF_Y, OFF_FIN, Cch, HIDd, EPI_RES_F);
    tout_kernel<<<dim3(12, 56, 32), 256>>>(out);
}

// round 10
// speedup vs baseline: 4.7536x; 1.1692x over previous
#include <cuda_runtime.h>
#include <cuda_fp16.h>
#include <math.h>
#include <stdint.h>

// ---------------- problem constants ----------------
#define Bsz   32
#define Cch   384
#define Hh    56
#define Wwid  56
#define WS    7
#define SSH   3
#define NHd   12
#define Ntok  49
#define HDim  32
#define HIDd  1536
#define NWTOT 2048
#define Mrows (NWTOT*Ntok)         // 100352
#define SCALE 0.17677669529663687f

// ---------------- scratch ----------------
constexpr size_t OFF_XRAW = 0;                                  // [M,384] f32
constexpr size_t OFF_Y    = OFF_XRAW + (size_t)Mrows*Cch;       // [M,384] f32
constexpr size_t OFF_FIN  = OFF_Y    + (size_t)Mrows*Cch;       // [M,384] f32
constexpr size_t SCRATCH_F = OFF_FIN + (size_t)Mrows*Cch;

constexpr size_t HOFF_XLN  = 0;
constexpr size_t HOFF_QKV  = HOFF_XLN  + (size_t)Mrows*Cch;
constexpr size_t HOFF_ATT  = HOFF_QKV  + (size_t)Mrows*(3*Cch);
constexpr size_t HOFF_YLN  = HOFF_ATT  + (size_t)Mrows*Cch;
constexpr size_t HOFF_H    = HOFF_YLN  + (size_t)Mrows*Cch;
constexpr size_t HOFF_WQKV = HOFF_H    + (size_t)Mrows*HIDd;
constexpr size_t HOFF_WPRJ = HOFF_WQKV + (size_t)1152*384;
constexpr size_t HOFF_WFC1 = HOFF_WPRJ + (size_t)384*384;
constexpr size_t HOFF_WFC2 = HOFF_WFC1 + (size_t)1536*384;
constexpr size_t SCRATCH_H = HOFF_WFC2 + (size_t)384*1536;

__device__ __align__(16) float  g_f[SCRATCH_F];
__device__ __align__(16) __half g_h[SCRATCH_H];

// ---------------- helpers ----------------
__device__ __forceinline__ int region(int p) {
    return p < (Hh - WS) ? 0 : (p < (Hh - SSH) ? 1 : 2);
}
__device__ __forceinline__ float gelu_exact(float v) {
    return 0.5f * v * (1.0f + erff(v * 0.70710678118654752f));
}
__device__ __forceinline__ void mma_f16(float c[4], const uint32_t a[4], const uint32_t b[2]) {
    asm volatile(
        "mma.sync.aligned.m16n8k16.row.col.f32.f16.f16.f32 "
        "{%0,%1,%2,%3}, {%4,%5,%6,%7}, {%8,%9}, {%0,%1,%2,%3};\n"
        : "+f"(c[0]), "+f"(c[1]), "+f"(c[2]), "+f"(c[3])
        : "r"(a[0]), "r"(a[1]), "r"(a[2]), "r"(a[3]), "r"(b[0]), "r"(b[1]));
}
__device__ __forceinline__ void cpa16(uint32_t dst, const void* src) {
    asm volatile("cp.async.cg.shared.global [%0], [%1], 16;" :: "r"(dst), "l"(src));
}
__device__ __forceinline__ void cpa_commit() {
    asm volatile("cp.async.commit_group;" ::: "memory");
}
template <int N>
__device__ __forceinline__ void cpa_wait() {
    asm volatile("cp.async.wait_group %0;" :: "n"(N) : "memory");
}

// ---------------- fused transpose-in + LN1 ----------------
// block per (hh, b). Loads x[b,:,h0,:] (384x56), LN per token, writes
// XRAW f32 (shortcut, m-order) and XLN half (GEMM A operand).
#define XS_STRIDE 57
constexpr int SMEM_TIN_BYTES = 384 * XS_STRIDE * 4;   // 87552

__global__ void __launch_bounds__(256) tinln_kernel(
    const float* __restrict__ x, const float* __restrict__ gam,
    const float* __restrict__ bet)
{
    extern __shared__ float xs[];   // [384][57]
    int hh = blockIdx.x, b = blockIdx.y;
    int tid = threadIdx.x;
    int h0 = hh + SSH; if (h0 >= Hh) h0 -= Hh;

    const float* src = x + ((size_t)b*Cch)*(Hh*Wwid) + h0*Wwid;
    for (int e = tid; e < 384*56; e += 256) {
        int c = e / 56, ws = e - c*56;
        xs[c*XS_STRIDE + ws] = src[(size_t)c*(Hh*Wwid) + ws];
    }
    __syncthreads();

    int warp = tid >> 5, lane = tid & 31;
    int wh = hh / WS, r = hh % WS;

    // per-warp cached gamma/beta for its 12 dims
    float gm[12], bt[12];
    #pragma unroll
    for (int j = 0; j < 12; j++) { gm[j] = gam[lane + 32*j]; bt[j] = bet[lane + 32*j]; }

    for (int ts = warp*7; ts < warp*7 + 7; ts++) {      // shifted col 0..55
        int wsrc = ts + SSH; if (wsrc >= Wwid) wsrc -= Wwid;
        float v[12];
        float s = 0.f, s2 = 0.f;
        #pragma unroll
        for (int j = 0; j < 12; j++) {
            float t = xs[(lane + 32*j)*XS_STRIDE + wsrc];
            v[j] = t; s += t; s2 += t*t;
        }
        #pragma unroll
        for (int o = 16; o; o >>= 1) {
            s  += __shfl_xor_sync(0xffffffffu, s,  o);
            s2 += __shfl_xor_sync(0xffffffffu, s2, o);
        }
        float mean = s * (1.0f/Cch);
        float var  = s2 * (1.0f/Cch) - mean*mean;
        float inv  = rsqrtf(var + 1e-5f);

        int ww = ts / WS, cc = ts % WS;
        int m = (((b*8 + wh)*8 + ww)*Ntok) + r*WS + cc;
        float*  xr = g_f + OFF_XRAW + (size_t)m*Cch;
        __half* xl = g_h + HOFF_XLN + (size_t)m*Cch;
        #pragma unroll
        for (int j = 0; j < 12; j++) {
            int d = lane + 32*j;
            xr[d] = v[j];
            xl[d] = __float2half_rn((v[j]-mean)*inv*gm[j] + bt[j]);
        }
    }
}

// ---------------- transpose-out ----------------
__global__ void __launch_bounds__(256) tout_kernel(float* __restrict__ out) {
    int ct = blockIdx.x, h0 = blockIdx.y, b = blockIdx.z;
    __shared__ float tile[32][57];
    int hh = h0 - SSH; if (hh < 0) hh += Hh;
    int wh = hh / WS, r = hh % WS;
    for (int idx = threadIdx.x; idx < 56*32; idx += 256) {
        int t = idx >> 5, i = idx & 31;
        int ww = t / WS, c = t % WS;
        int m = (((b*8 + wh)*8 + ww)*Ntok) + r*WS + c;
        int w0 = t + SSH; if (w0 >= Wwid) w0 -= Wwid;
        tile[i][w0] = g_f[OFF_FIN + (size_t)m*Cch + ct*32 + i];
    }
    __syncthreads();
    for (int idx = threadIdx.x; idx < 32*56; idx += 256) {
        int i = idx / 56, w0 = idx - i*56;
        out[((size_t)(b*Cch + ct*32 + i))*(Hh*Wwid) + h0*Wwid + w0] = tile[i][w0];
    }
}

// ---------------- weight transpose [K][N] f32 -> [N][K] half ----------------
__global__ void __launch_bounds__(256) wtrans_kernel(const float* __restrict__ W,
                                                     int K, int N, size_t outoff) {
    __shared__ float t[32][33];
    int n0 = blockIdx.x*32, k0 = blockIdx.y*32;
    int tx = threadIdx.x & 31, ty = threadIdx.x >> 5;
    __half* out = g_h + outoff;
    for (int i = ty; i < 32; i += 8)
        t[i][tx] = W[(size_t)(k0+i)*N + n0+tx];
    __syncthreads();
    for (int i = ty; i < 32; i += 8)
        out[(size_t)(n0+i)*K + k0+tx] = __float2half_rn(t[tx][i]);
}

// ---------------- layernorm2: fp32 in -> fp16 out ----------------
__global__ void __launch_bounds__(128) ln_kernel(size_t Xoff, const float* __restrict__ gam,
                                                 const float* __restrict__ bet, size_t Yoff) {
    int row = blockIdx.x;
    const float* x = g_f + Xoff + (size_t)row*Cch;
    __half*      y = g_h + Yoff + (size_t)row*Cch;
    int c = threadIdx.x;
    float v0 = x[c], v1 = x[c+128], v2 = x[c+256];
    float s = v0+v1+v2, s2 = v0*v0 + v1*v1 + v2*v2;
    #pragma unroll
    for (int o = 16; o; o >>= 1) {
        s  += __shfl_xor_sync(0xffffffffu, s,  o);
        s2 += __shfl_xor_sync(0xffffffffu, s2, o);
    }
    __shared__ float rs[4], rs2[4];
    int wid = c >> 5;
    if ((c & 31) == 0) { rs[wid] = s; rs2[wid] = s2; }
    __syncthreads();
    s  = rs[0]+rs[1]+rs[2]+rs[3];
    s2 = rs2[0]+rs2[1]+rs2[2]+rs2[3];
    float mean = s * (1.0f/Cch);
    float var  = s2 * (1.0f/Cch) - mean*mean;
    float inv  = rsqrtf(var + 1e-5f);
    y[c]     = __float2half_rn((v0-mean)*inv*gam[c]     + bet[c]);
    y[c+128] = __float2half_rn((v1-mean)*inv*gam[c+128] + bet[c+128]);
    y[c+256] = __float2half_rn((v2-mean)*inv*gam[c+256] + bet[c+256]);
}

// ---------------- fp16 GEMM: packed tiles + k-slot-relabeled LDS.64 frags ----
#define EPI_BIAS_H 0
#define EPI_RES_F  1
#define EPI_GELU_H 2

#define HT_STG (128*16)          // halves per tile (A or B), packed [row][16]
#define STAGES 4
constexpr int SMEM_HGEMM_BYTES = STAGES * 2 * HT_STG * 2;   // 32768

__global__ void __launch_bounds__(256, 2) hgemm_kernel(
    size_t Aoff, size_t Boff, const float* __restrict__ bias,
    long long resoff, size_t Coff, int N, int K, int epi)
{
    extern __shared__ __half smh[];
    __half* As = smh;                    // [STAGES][128*16]
    __half* Bs = smh + STAGES*HT_STG;    // [STAGES][128*16]
    uint32_t as_sm = (uint32_t)__cvta_generic_to_shared(As);
    uint32_t bs_sm = (uint32_t)__cvta_generic_to_shared(Bs);

    int tid = threadIdx.x;
    int warp = tid >> 5, lane = tid & 31;
    int wrow = warp >> 2, wcol = warp & 3;
    int g = lane >> 2, qc = lane & 3;
    int brow = blockIdx.y, bcol = blockIdx.x;

    const __half* Ablk = g_h + Aoff + (size_t)brow*128*K;
    const __half* Bblk = g_h + Boff + (size_t)bcol*128*K;

    int lrow = tid >> 1;
    int lch  = (tid & 1) * 8;

    auto load_tile = [&](int s, int kt) {
        const __half* Ap = Ablk + (size_t)lrow*K + kt*16 + lch;
        const __half* Bp = Bblk + (size_t)lrow*K + kt*16 + lch;
        uint32_t off = (uint32_t)(s*HT_STG + lrow*16 + lch) * 2;
        cpa16(as_sm + off, Ap);
        cpa16(bs_sm + off, Bp);
    };

    float acc[4][4][4];
    #pragma unroll
    for (int i = 0; i < 4; i++)
        #pragma unroll
        for (int j = 0; j < 4; j++)
            #pragma unroll
            for (int r = 0; r < 4; r++) acc[i][j][r] = 0.f;

    int nk = K >> 4;
    load_tile(0, 0); cpa_commit();
    load_tile(1, 1); cpa_commit();
    load_tile(2, 2); cpa_commit();
    cpa_wait<2>();
    __syncthreads();

    int stage = 0;
    for (int kt = 0; kt < nk; kt++) {
        if (kt + 3 < nk) {
            int s = stage + 3 >= STAGES ? stage + 3 - STAGES : stage + 3;
            load_tile(s, kt + 3);
        }
        cpa_commit();

        const __half* Asb = As + stage*HT_STG;
        const __half* Bsb = Bs + stage*HT_STG;
        // k-slot relabel: thread qc uses k {4qc,4qc+1} (low) and {4qc+2,4qc+3}
        // (high) — A and B agree, so the k-sum is unchanged. Fragments are
        // contiguous 8B -> LDS.64, conflict-free (word = 8g+2qc mod 32).
        uint32_t af[4][4];
        #pragma unroll
        for (int i = 0; i < 4; i++) {
            int r = wrow*64 + i*16 + g;
            uint2 lo = *(const uint2*)(Asb + r*16     + 4*qc);
            uint2 hi = *(const uint2*)(Asb + (r+8)*16 + 4*qc);
            af[i][0] = lo.x; af[i][1] = hi.x; af[i][2] = lo.y; af[i][3] = hi.y;
        }
        uint32_t bf[4][2];
        #pragma unroll
        for (int j = 0; j < 4; j++) {
            int c = wcol*32 + j*8 + g;
            uint2 bb = *(const uint2*)(Bsb + c*16 + 4*qc);
            bf[j][0] = bb.x; bf[j][1] = bb.y;
        }
        #pragma unroll
        for (int i = 0; i < 4; i++)
            #pragma unroll
            for (int j = 0; j < 4; j++)
                mma_f16(acc[i][j], af[i], bf[j]);

        cpa_wait<2>();
        __syncthreads();
        stage = stage + 1 == STAGES ? 0 : stage + 1;
    }

    const float* res = (resoff >= 0) ? (g_f + (size_t)resoff) : nullptr;
    #pragma unroll
    for (int i = 0; i < 4; i++) {
        int r0 = brow*128 + wrow*64 + i*16 + g;
        #pragma unroll
        for (int j = 0; j < 4; j++) {
            int cb = bcol*128 + wcol*32 + j*8 + qc*2;
            float bx = bias[cb], by = bias[cb+1];
            #pragma unroll
            for (int half_ = 0; half_ < 2; half_++) {
                int row = r0 + half_*8;
                float vx = acc[i][j][half_*2]   + bx;
                float vy = acc[i][j][half_*2+1] + by;
                if (epi == EPI_RES_F) {
                    float2 rr = *(const float2*)(res + (size_t)row*N + cb);
                    vx += rr.x; vy += rr.y;
                    float2 o = {vx, vy};
                    *(float2*)(g_f + Coff + (size_t)row*N + cb) = o;
                } else {
                    if (epi == EPI_GELU_H) { vx = gelu_exact(vx); vy = gelu_exact(vy); }
                    *(__half2*)(g_h + Coff + (size_t)row*N + cb) =
                        __floats2half2_rn(vx, vy);
                }
            }
        }
    }
}

// ---------------- tensor-core windowed attention (round-9, passing) ----------
__global__ void __launch_bounds__(128) attn_kernel(const float* __restrict__ rpb) {
    int blk = blockIdx.x;
    int h = blk % NHd;
    int w = blk / NHd;
    int ww = w & 7, wh = (w >> 3) & 7;
    int m0 = w * Ntok;

    __shared__ __half qh[64][40];
    __shared__ __half kh[56][40];
    __shared__ __half vT[32][72];
    __shared__ float  P[49][60];
    __shared__ __half Ph[64][72];
    __shared__ int    rid[Ntok];

    int tid = threadIdx.x;
    int warp = tid >> 5, lane = tid & 31;
    int g = lane >> 2, qc = lane & 3;

    {
        uint32_t* z1 = (uint32_t*)&vT[0][0];
        #pragma unroll 4
        for (int i = tid; i < 32*72/2; i += 128) z1[i] = 0;
        uint32_t* z2 = (uint32_t*)&Ph[0][0];
        #pragma unroll 4
        for (int i = tid; i < 64*72/2; i += 128) z2[i] = 0;
    }
    __syncthreads();

    const __half* qkv = g_h + HOFF_QKV;
    if (tid < 98) {
        int i = tid >> 1, p = tid & 1;
        const __half* base = qkv + (size_t)(m0 + i)*(3*Cch) + h*HDim + p*16;
        *(uint4*)&qh[i][p*16]     = *(const uint4*)(base);
        *(uint4*)&qh[i][p*16 + 8] = *(const uint4*)(base + 8);
        *(uint4*)&kh[i][p*16]     = *(const uint4*)(base + Cch);
        *(uint4*)&kh[i][p*16 + 8] = *(const uint4*)(base + Cch + 8);
        const __half* vbase = base + 2*Cch;
        #pragma unroll
        for (int d = 0; d < 16; d++)
            vT[p*16 + d][i] = vbase[d];
    }
    if (tid < Ntok) {
        int r = tid / WS, c = tid % WS;
        rid[tid] = region(wh*WS + r)*3 + region(ww*WS + c);
    }
    __syncthreads();

    {
        int r = warp*16 + g;
        uint32_t af[2][4];
        #pragma unroll
        for (int kc = 0; kc < 2; kc++) {
            af[kc][0] = *(const uint32_t*)&qh[r][kc*16 + 2*qc];
            af[kc][1] = *(const uint32_t*)&qh[r+8][kc*16 + 2*qc];
            af[kc][2] = *(const uint32_t*)&qh[r][kc*16 + 2*qc + 8];
            af[kc][3] = *(const uint32_t*)&qh[r+8][kc*16 + 2*qc + 8];
        }
        #pragma unroll
        for (int jt = 0; jt < 7; jt++) {
            float c4[4] = {0.f, 0.f, 0.f, 0.f};
            int col = jt*8 + g;
            uint32_t bf0[2], bf1[2];
            bf0[0] = *(const uint32_t*)&kh[col][2*qc];
            bf0[1] = *(const uint32_t*)&kh[col][2*qc + 8];
            bf1[0] = *(const uint32_t*)&kh[col][16 + 2*qc];
            bf1[1] = *(const uint32_t*)&kh[col][16 + 2*qc + 8];
            mma_f16(c4, af[0], bf0);
            mma_f16(c4, af[1], bf1);
            int c0 = jt*8 + 2*qc;
            #pragma unroll
            for (int u = 0; u < 4; u++) {
                int row = r + (u >> 1)*8;
                int ccol = c0 + (u & 1);
                if (row < Ntok && ccol < Ntok) {
                    int ri = row/WS, ci = row%WS, rj = ccol/WS, cj = ccol%WS;
                    int rpi = (ri - rj + 6)*13 + (ci - cj + 6);
                    float s = c4[u]*SCALE + rpb[rpi*NHd + h];
                    if (rid[row] != rid[ccol]) s -= 100.f;
                    P[row][ccol] = s;
                }
            }
        }
    }
    __syncthreads();

    {
        int i = tid >> 1, p = tid & 1;
        bool act = (tid < 98);
        int ic = act ? i : 0;
        float mx = -1e30f;
        for (int j = p; j < Ntok; j += 2) mx = fmaxf(mx, P[ic][j]);
        mx = fmaxf(mx, __shfl_xor_sync(0xffffffffu, mx, 1));
        float sum = 0.f;
        for (int j = p; j < Ntok; j += 2) sum += __expf(P[ic][j] - mx);
        sum += __shfl_xor_sync(0xffffffffu, sum, 1);
        float inv = 1.0f / sum;
        if (act)
            for (int j = p; j < Ntok; j += 2)
                Ph[ic][j] = __float2half_rn(__expf(P[ic][j] - mx) * inv);
    }
    __syncthreads();

    {
        int r = warp*16 + g;
        uint32_t af[4][4];
        #pragma unroll
        for (int kc = 0; kc < 4; kc++) {
            af[kc][0] = *(const uint32_t*)&Ph[r][kc*16 + 2*qc];
            af[kc][1] = *(const uint32_t*)&Ph[r+8][kc*16 + 2*qc];
            af[kc][2] = *(const uint32_t*)&Ph[r][kc*16 + 2*qc + 8];
            af[kc][3] = *(const uint32_t*)&Ph[r+8][kc*16 + 2*qc + 8];
        }
        __half* att = g_h + HOFF_ATT;
        #pragma unroll
        for (int ct = 0; ct < 4; ct++) {
            float c4[4] = {0.f, 0.f, 0.f, 0.f};
            int dcol = ct*8 + g;
            #pragma unroll
            for (int kc = 0; kc < 4; kc++) {
                uint32_t bf[2];
                bf[0] = *(const uint32_t*)&vT[dcol][kc*16 + 2*qc];
                bf[1] = *(const uint32_t*)&vT[dcol][kc*16 + 2*qc + 8];
                mma_f16(c4, af[kc], bf);
            }
            int c0 = ct*8 + 2*qc;
            if (r < Ntok)
                *(__half2*)(att + (size_t)(m0 + r)*Cch + h*HDim + c0) =
                    __floats2half2_rn(c4[0], c4[1]);
            if (r + 8 < Ntok)
                *(__half2*)(att + (size_t)(m0 + r + 8)*Cch + h*HDim + c0) =
                    __floats2half2_rn(c4[2], c4[3]);
        }
    }
}

// ---------------- launch ----------------
extern "C" void kernel_launch(void* const* d_in, const int* in_sizes, int n_in,
                              void* d_out, int out_size) {
    const float* x      = (const float*)d_in[0];
    const float* qkv_w  = (const float*)d_in[1];
    const float* qkv_b  = (const float*)d_in[2];
    const float* proj_w = (const float*)d_in[3];
    const float* proj_b = (const float*)d_in[4];
    const float* rpb    = (const float*)d_in[5];
    const float* n1w    = (const float*)d_in[6];
    const float* n1b    = (const float*)d_in[7];
    const float* n2w    = (const float*)d_in[8];
    const float* n2b    = (const float*)d_in[9];
    const float* fc1w   = (const float*)d_in[10];
    const float* fc1b   = (const float*)d_in[11];
    const float* fc2w   = (const float*)d_in[12];
    const float* fc2b   = (const float*)d_in[13];
    float* out = (float*)d_out;

    cudaFuncSetAttribute(hgemm_kernel, cudaFuncAttributeMaxDynamicSharedMemorySize,
                         SMEM_HGEMM_BYTES);
    cudaFuncSetAttribute(tinln_kernel, cudaFuncAttributeMaxDynamicSharedMemorySize,
                         SMEM_TIN_BYTES);

    wtrans_kernel<<<dim3(1152/32, 384/32), 256>>>(qkv_w, Cch, 1152, HOFF_WQKV);
    wtrans_kernel<<<dim3(384/32,  384/32), 256>>>(proj_w, Cch, 384,  HOFF_WPRJ);
    wtrans_kernel<<<dim3(1536/32, 384/32), 256>>>(fc1w,  Cch, 1536, HOFF_WFC1);
    wtrans_kernel<<<dim3(384/32, 1536/32), 256>>>(fc2w,  HIDd, 384, HOFF_WFC2);

    tinln_kernel<<<dim3(56, 32), 256, SMEM_TIN_BYTES>>>(x, n1w, n1b);
    hgemm_kernel<<<dim3(1152/128, Mrows/128), 256, SMEM_HGEMM_BYTES>>>(
        HOFF_XLN, HOFF_WQKV, qkv_b, -1, HOFF_QKV, 1152, Cch, EPI_BIAS_H);
    attn_kernel<<<NWTOT * NHd, 128>>>(rpb);
    hgemm_kernel<<<dim3(384/128, Mrows/128), 256, SMEM_HGEMM_BYTES>>>(
        HOFF_ATT, HOFF_WPRJ, proj_b, (long long)OFF_XRAW, OFF_Y, Cch, Cch, EPI_RES_F);
    ln_kernel<<<Mrows, 128>>>(OFF_Y, n2w, n2b, HOFF_YLN);
    hgemm_kernel<<<dim3(1536/128, Mrows/128), 256, SMEM_HGEMM_BYTES>>>(
        HOFF_YLN, HOFF_WFC1, fc1b, -1, HOFF_H, HIDd, Cch, EPI_GELU_H);
    hgemm_kernel<<<dim3(384/128, Mrows/128), 256, SMEM_HGEMM_BYTES>>>(
        HOFF_H, HOFF_WFC2, fc2b, (long long)OFF_Y, OFF_FIN, Cch, HIDd, EPI_RES_F);
    tout_kernel<<<dim3(12, 56, 32), 256>>>(out);
}